// round 1
// baseline (speedup 1.0000x reference)
#include <cuda_runtime.h>

// ---------------------------------------------------------------------------
// Model_63256278335531: 2-layer dual-GCN forward on GB300.
//   Layer l, branch t in {adj,diff}, sign x in {pos,neg}:
//     fts = X @ W_t_l          (8192x512 @ 512x512)
//     h   = prelu(A_t @ fts + b, a)   (8192x8192 @ 8192x512)
//   pos/neg share A_t and W, so their fts are packed side-by-side into a
//   [8192 x 1024] matrix and each big GEMM does N=1024 in one pass.
// ---------------------------------------------------------------------------

// Scratch for packed fts matrices (cols 0..511 = pos branch, 512..1023 = neg).
__device__ float g_ftsA[8192ull * 1024ull];
__device__ float g_ftsD[8192ull * 1024ull];

#define BM 128
#define BN 128
#define BK 16

// Generic fp32 SGEMM, 128x128x16 tiles, 256 threads, 8x8 per thread.
// PRELU=false: C0[gr*ldc + gc] = acc                  (N must be 512 here)
// PRELU=true : v = prelu(acc + bias[gc&511], *alphap);
//              (gc<512 ? C0 : C1)[gr*512 + (gc&511)] = v   (N = 1024)
template <bool PRELU>
__global__ void __launch_bounds__(256)
sgemm_k(const float* __restrict__ A, const float* __restrict__ B,
        float* __restrict__ C0, float* __restrict__ C1,
        int K, int lda, int ldb, int ldc,
        const float* __restrict__ bias, const float* __restrict__ alphap)
{
    __shared__ float As[2][BK][BM];   // transposed: As[k][m]
    __shared__ float Bs[2][BK][BN];   // Bs[k][n]

    const int tid = threadIdx.x;
    const int tx = tid & 15;          // column group 0..15
    const int ty = tid >> 4;          // row group 0..15
    const int bx = blockIdx.x;        // N tile
    const int by = blockIdx.y;        // M tile

    const float* Ab = A + (size_t)by * BM * lda;
    const float* Bb = B + (size_t)bx * BN;

    // Global-load assignments (each thread: 2 float4 from A, 2 from B).
    const int ar0 = tid >> 2;                 // 0..63  (and +64 for second)
    const int ak0 = (tid & 3) << 2;           // 0,4,8,12
    const int bk0 = tid >> 5;                 // 0..7   (and +8 for second)
    const int bc0 = (tid & 31) << 2;          // 0..124

    float4 a0v, a1v, b0v, b1v;

    // Prologue: tile 0
    a0v = *(const float4*)(Ab + (size_t)ar0 * lda + ak0);
    a1v = *(const float4*)(Ab + (size_t)(ar0 + 64) * lda + ak0);
    b0v = *(const float4*)(Bb + (size_t)bk0 * ldb + bc0);
    b1v = *(const float4*)(Bb + (size_t)(bk0 + 8) * ldb + bc0);

    As[0][ak0 + 0][ar0] = a0v.x;
    As[0][ak0 + 1][ar0] = a0v.y;
    As[0][ak0 + 2][ar0] = a0v.z;
    As[0][ak0 + 3][ar0] = a0v.w;
    As[0][ak0 + 0][ar0 + 64] = a1v.x;
    As[0][ak0 + 1][ar0 + 64] = a1v.y;
    As[0][ak0 + 2][ar0 + 64] = a1v.z;
    As[0][ak0 + 3][ar0 + 64] = a1v.w;
    *(float4*)&Bs[0][bk0][bc0]     = b0v;
    *(float4*)&Bs[0][bk0 + 8][bc0] = b1v;
    __syncthreads();

    float acc[8][8];
#pragma unroll
    for (int i = 0; i < 8; ++i)
#pragma unroll
        for (int j = 0; j < 8; ++j) acc[i][j] = 0.0f;

    const int ntiles = K >> 4;
    int cur = 0;
    for (int kt = 0; kt < ntiles; ++kt) {
        const bool has_next = (kt + 1 < ntiles);
        if (has_next) {
            const float* An = Ab + ((size_t)(kt + 1) << 4);
            const float* Bn = Bb + ((size_t)(kt + 1) << 4) * ldb;
            a0v = *(const float4*)(An + (size_t)ar0 * lda + ak0);
            a1v = *(const float4*)(An + (size_t)(ar0 + 64) * lda + ak0);
            b0v = *(const float4*)(Bn + (size_t)bk0 * ldb + bc0);
            b1v = *(const float4*)(Bn + (size_t)(bk0 + 8) * ldb + bc0);
        }
#pragma unroll
        for (int k = 0; k < BK; ++k) {
            float a[8], b[8];
            *(float4*)&a[0] = *(const float4*)&As[cur][k][ty * 4];
            *(float4*)&a[4] = *(const float4*)&As[cur][k][ty * 4 + 64];
            *(float4*)&b[0] = *(const float4*)&Bs[cur][k][tx * 4];
            *(float4*)&b[4] = *(const float4*)&Bs[cur][k][tx * 4 + 64];
#pragma unroll
            for (int i = 0; i < 8; ++i)
#pragma unroll
                for (int j = 0; j < 8; ++j)
                    acc[i][j] = fmaf(a[i], b[j], acc[i][j]);
        }
        if (has_next) {
            cur ^= 1;
            As[cur][ak0 + 0][ar0] = a0v.x;
            As[cur][ak0 + 1][ar0] = a0v.y;
            As[cur][ak0 + 2][ar0] = a0v.z;
            As[cur][ak0 + 3][ar0] = a0v.w;
            As[cur][ak0 + 0][ar0 + 64] = a1v.x;
            As[cur][ak0 + 1][ar0 + 64] = a1v.y;
            As[cur][ak0 + 2][ar0 + 64] = a1v.z;
            As[cur][ak0 + 3][ar0 + 64] = a1v.w;
            *(float4*)&Bs[cur][bk0][bc0]     = b0v;
            *(float4*)&Bs[cur][bk0 + 8][bc0] = b1v;
            __syncthreads();
        }
    }

    // Epilogue
    const float al = PRELU ? *alphap : 0.0f;
#pragma unroll
    for (int ih = 0; ih < 2; ++ih) {
#pragma unroll
        for (int jh = 0; jh < 2; ++jh) {
            const int gc0 = bx * BN + tx * 4 + jh * 64;  // 4 contiguous cols
            float4 bv = make_float4(0.f, 0.f, 0.f, 0.f);
            int ch = 0;
            float* Cd = C0;
            if (PRELU) {
                ch = gc0 & 511;
                bv = *(const float4*)&bias[ch];
                Cd = (gc0 < 512) ? C0 : C1;
            }
#pragma unroll
            for (int i = 0; i < 4; ++i) {
                const int gr = by * BM + ty * 4 + i + ih * 64;
                float4 v;
                v.x = acc[ih * 4 + i][jh * 4 + 0];
                v.y = acc[ih * 4 + i][jh * 4 + 1];
                v.z = acc[ih * 4 + i][jh * 4 + 2];
                v.w = acc[ih * 4 + i][jh * 4 + 3];
                if (PRELU) {
                    v.x += bv.x; v.y += bv.y; v.z += bv.z; v.w += bv.w;
                    v.x = v.x >= 0.f ? v.x : al * v.x;
                    v.y = v.y >= 0.f ? v.y : al * v.y;
                    v.z = v.z >= 0.f ? v.z : al * v.z;
                    v.w = v.w >= 0.f ? v.w : al * v.w;
                    *(float4*)&Cd[(size_t)gr * 512 + ch] = v;
                } else {
                    *(float4*)&C0[(size_t)gr * ldc + gc0] = v;
                }
            }
        }
    }
}

extern "C" void kernel_launch(void* const* d_in, const int* in_sizes, int n_in,
                              void* d_out, int out_size)
{
    const float* seq_pos = (const float*)d_in[0];
    const float* seq_neg = (const float*)d_in[1];
    const float* adj     = (const float*)d_in[2];
    const float* diff    = (const float*)d_in[3];
    const float* W_adj1  = (const float*)d_in[4];
    const float* W_diff1 = (const float*)d_in[5];
    const float* W_adj2  = (const float*)d_in[6];
    const float* W_diff2 = (const float*)d_in[7];
    const float* b_adj1  = (const float*)d_in[8];
    const float* b_diff1 = (const float*)d_in[9];
    const float* b_adj2  = (const float*)d_in[10];
    const float* b_diff2 = (const float*)d_in[11];
    const float* a_adj1  = (const float*)d_in[12];
    const float* a_diff1 = (const float*)d_in[13];
    const float* a_adj2  = (const float*)d_in[14];
    const float* a_diff2 = (const float*)d_in[15];

    float* out = (float*)d_out;
    const size_t CHN = (size_t)8192 * 512;   // one output chunk

    float *ftsA = nullptr, *ftsD = nullptr;
    cudaGetSymbolAddress((void**)&ftsA, g_ftsA);
    cudaGetSymbolAddress((void**)&ftsD, g_ftsD);

    dim3 blk(256);
    dim3 gSmall(512 / BN, 8192 / BM);    // 4 x 64
    dim3 gBig(1024 / BN, 8192 / BM);     // 8 x 64

    // ---- Layer 1: fts = seq @ W1, packed [pos | neg] into 1024 cols ----
    sgemm_k<false><<<gSmall, blk>>>(seq_pos, W_adj1,  ftsA + 0,   nullptr, 512, 512, 512, 1024, nullptr, nullptr);
    sgemm_k<false><<<gSmall, blk>>>(seq_neg, W_adj1,  ftsA + 512, nullptr, 512, 512, 512, 1024, nullptr, nullptr);
    sgemm_k<false><<<gSmall, blk>>>(seq_pos, W_diff1, ftsD + 0,   nullptr, 512, 512, 512, 1024, nullptr, nullptr);
    sgemm_k<false><<<gSmall, blk>>>(seq_neg, W_diff1, ftsD + 512, nullptr, 512, 512, 512, 1024, nullptr, nullptr);

    // ---- Layer 1: h1 = prelu(A @ fts + b) ----
    // out chunks: 0=h_a1_p 1=h_d1_p 2=h_a2_p 3=h_d2_p 4=h_a1_n 5=h_d1_n 6=h_a2_n 7=h_d2_n
    sgemm_k<true><<<gBig, blk>>>(adj,  ftsA, out + 0 * CHN, out + 4 * CHN, 8192, 8192, 1024, 512, b_adj1,  a_adj1);
    sgemm_k<true><<<gBig, blk>>>(diff, ftsD, out + 1 * CHN, out + 5 * CHN, 8192, 8192, 1024, 512, b_diff1, a_diff1);

    // ---- Layer 2: fts2 = h1 @ W2 ----
    sgemm_k<false><<<gSmall, blk>>>(out + 0 * CHN, W_adj2,  ftsA + 0,   nullptr, 512, 512, 512, 1024, nullptr, nullptr);
    sgemm_k<false><<<gSmall, blk>>>(out + 4 * CHN, W_adj2,  ftsA + 512, nullptr, 512, 512, 512, 1024, nullptr, nullptr);
    sgemm_k<false><<<gSmall, blk>>>(out + 1 * CHN, W_diff2, ftsD + 0,   nullptr, 512, 512, 512, 1024, nullptr, nullptr);
    sgemm_k<false><<<gSmall, blk>>>(out + 5 * CHN, W_diff2, ftsD + 512, nullptr, 512, 512, 512, 1024, nullptr, nullptr);

    // ---- Layer 2: h2 = prelu(A @ fts2 + b) ----
    sgemm_k<true><<<gBig, blk>>>(adj,  ftsA, out + 2 * CHN, out + 6 * CHN, 8192, 8192, 1024, 512, b_adj2,  a_adj2);
    sgemm_k<true><<<gBig, blk>>>(diff, ftsD, out + 3 * CHN, out + 7 * CHN, 8192, 8192, 1024, 512, b_diff2, a_diff2);
}

// round 7
// speedup vs baseline: 3.4493x; 3.4493x over previous
#include <cuda_runtime.h>
#include <cuda_bf16.h>
#include <stdint.h>

// Model_63256278335531: 2-layer dual-GCN via bf16x3 mma.sync (HMMA) GEMMs.
// D = Ah*Bh + Ah*Bl + Al*Bh (fp32 register accumulate) ~ fp32-accurate.

#define NEL_ADJ (8192ull*8192ull)
#define NEL_SEQ (8192ull*512ull)
#define NEL_W   (512ull*512ull)
#define NEL_FTS (8192ull*1024ull)

__device__ __align__(16) __nv_bfloat16 g_adjHi[NEL_ADJ];
__device__ __align__(16) __nv_bfloat16 g_adjLo[NEL_ADJ];
__device__ __align__(16) __nv_bfloat16 g_difHi[NEL_ADJ];
__device__ __align__(16) __nv_bfloat16 g_difLo[NEL_ADJ];
__device__ __align__(16) __nv_bfloat16 g_spHi[NEL_SEQ], g_spLo[NEL_SEQ];
__device__ __align__(16) __nv_bfloat16 g_snHi[NEL_SEQ], g_snLo[NEL_SEQ];
__device__ __align__(16) __nv_bfloat16 g_wHi[4][NEL_W], g_wLo[4][NEL_W];
// fts as B operand of big GEMM: [K=8192][N=1024] (pos cols 0-511, neg 512-1023)
__device__ __align__(16) __nv_bfloat16 g_ftAHi[NEL_FTS], g_ftALo[NEL_FTS];
__device__ __align__(16) __nv_bfloat16 g_ftDHi[NEL_FTS], g_ftDLo[NEL_FTS];
// h1 packed [M=8192][1024]: A operand for layer-2 small GEMM
__device__ __align__(16) __nv_bfloat16 g_hAHi[NEL_FTS], g_hALo[NEL_FTS];
__device__ __align__(16) __nv_bfloat16 g_hDHi[NEL_FTS], g_hDLo[NEL_FTS];

__device__ __forceinline__ uint32_t smem_u32(const void* p){
    uint32_t a;
    asm("{ .reg .u64 t; cvta.to.shared.u64 t, %1; cvt.u32.u64 %0, t; }"
        : "=r"(a) : "l"(p));
    return a;
}
__device__ __forceinline__ void cp16(uint32_t dst, const void* src){
    asm volatile("{ .reg .u64 g; cvta.to.global.u64 g, %1;"
                 " cp.async.cg.shared.global [%0], [g], 16; }"
                 :: "r"(dst), "l"(src) : "memory");
}
__device__ __forceinline__ void cp_commit(){
    asm volatile("cp.async.commit_group;" ::: "memory");
}
__device__ __forceinline__ void cp_wait2(){
    asm volatile("cp.async.wait_group 2;" ::: "memory");
}
__device__ __forceinline__ void ldsm_x4(uint32_t& r0, uint32_t& r1,
                                        uint32_t& r2, uint32_t& r3, uint32_t a){
    asm volatile("ldmatrix.sync.aligned.m8n8.x4.shared.b16 {%0,%1,%2,%3}, [%4];"
                 : "=r"(r0), "=r"(r1), "=r"(r2), "=r"(r3) : "r"(a));
}
__device__ __forceinline__ void ldsm_x4_t(uint32_t& r0, uint32_t& r1,
                                          uint32_t& r2, uint32_t& r3, uint32_t a){
    asm volatile("ldmatrix.sync.aligned.m8n8.x4.trans.shared.b16 {%0,%1,%2,%3}, [%4];"
                 : "=r"(r0), "=r"(r1), "=r"(r2), "=r"(r3) : "r"(a));
}
__device__ __forceinline__ void mma16816(float* c, uint32_t a0, uint32_t a1,
                                         uint32_t a2, uint32_t a3,
                                         uint32_t b0, uint32_t b1){
    asm volatile("mma.sync.aligned.m16n8k16.row.col.f32.bf16.bf16.f32 "
                 "{%0,%1,%2,%3}, {%4,%5,%6,%7}, {%8,%9}, {%0,%1,%2,%3};"
                 : "+f"(c[0]), "+f"(c[1]), "+f"(c[2]), "+f"(c[3])
                 : "r"(a0), "r"(a1), "r"(a2), "r"(a3), "r"(b0), "r"(b1));
}

__global__ void split_k(const float* __restrict__ x, __nv_bfloat16* __restrict__ hi,
                        __nv_bfloat16* __restrict__ lo, size_t n)
{
    size_t i = ((size_t)blockIdx.x * blockDim.x + threadIdx.x) * 4;
    if (i >= n) return;
    float4 v = *(const float4*)(x + i);
    __nv_bfloat16 h0 = __float2bfloat16_rn(v.x), h1 = __float2bfloat16_rn(v.y);
    __nv_bfloat16 h2 = __float2bfloat16_rn(v.z), h3 = __float2bfloat16_rn(v.w);
    __nv_bfloat16 l0 = __float2bfloat16_rn(v.x - __bfloat162float(h0));
    __nv_bfloat16 l1 = __float2bfloat16_rn(v.y - __bfloat162float(h1));
    __nv_bfloat16 l2 = __float2bfloat16_rn(v.z - __bfloat162float(h2));
    __nv_bfloat16 l3 = __float2bfloat16_rn(v.w - __bfloat162float(h3));
    __nv_bfloat162* H = (__nv_bfloat162*)(hi + i);
    H[0] = __halves2bfloat162(h0, h1); H[1] = __halves2bfloat162(h2, h3);
    __nv_bfloat162* L = (__nv_bfloat162*)(lo + i);
    L[0] = __halves2bfloat162(l0, l1); L[1] = __halves2bfloat162(l2, l3);
}

// CTA 128(M) x 128(N), K-stage 64, 3-stage cp.async pipeline.
// 8 warps: wm = wid&1 (M-halves of 64), wn = wid>>1 (N-quarters of 32).
// Stage layout: AH[128][64] AL BH[64][128] BL = 16KB each, 64KB/stage.
// A rows 128B (8x16B units), swizzle unit u -> u ^ (row&7).
// B rows 256B (16x16B units), same low-3-bit XOR swizzle.
// EPI=0: acc -> bf16 hi/lo into F[m*1024 + fcol + n]   (fts path, m is k-row)
// EPI=1: v = prelu(acc + bias[n&511]); fp32 -> (n<512?C0:C1)[m*512+(n&511)];
//        optional bf16 hi/lo h1 at H[m*1024+n].
#define STG_BYTES 65536
#define SMEM_DYN  (3*STG_BYTES)

template<int EPI>
__global__ void __launch_bounds__(256, 1)
gemm_mma(const __nv_bfloat16* __restrict__ Ahi, const __nv_bfloat16* __restrict__ Alo,
         long lda, long aofs,
         const __nv_bfloat16* __restrict__ Bhi, const __nv_bfloat16* __restrict__ Blo,
         long ldb, int K,
         __nv_bfloat16* __restrict__ Fhi, __nv_bfloat16* __restrict__ Flo, long fcol,
         float* __restrict__ C0, float* __restrict__ C1,
         const float* __restrict__ bias, const float* __restrict__ alphap,
         __nv_bfloat16* __restrict__ Hhi, __nv_bfloat16* __restrict__ Hlo)
{
    extern __shared__ __align__(1024) char smem[];
    const uint32_t sbase = smem_u32(smem);

    const int tid  = threadIdx.x;
    const int lane = tid & 31;
    const int wid  = tid >> 5;
    const int wm   = wid & 1;
    const int wn   = wid >> 1;
    const long arow = (long)blockIdx.y * 128;
    const long bn0  = (long)blockIdx.x * 128;
    const int  nk   = K >> 6;

    auto load_stage = [&](int st, int kc){
        uint32_t base = sbase + st * STG_BYTES;
        const long ka = aofs + (long)kc * 64;
        const long kb = (long)kc * 64;
        #pragma unroll
        for (int s = 0; s < 4; ++s){
            int idx = tid + 256 * s;
            int r = idx >> 3, u = idx & 7;      // A: 128 rows x 8 units
            uint32_t sw = (uint32_t)(r * 128 + ((u ^ (r & 7)) << 4));
            cp16(base + sw,         Ahi + (arow + r) * lda + ka + u * 8);
            cp16(base + 16384 + sw, Alo + (arow + r) * lda + ka + u * 8);
        }
        #pragma unroll
        for (int s = 0; s < 4; ++s){
            int idx = tid + 256 * s;
            int r = idx >> 4, u = idx & 15;     // B: 64 rows x 16 units
            uint32_t sw = (uint32_t)(r * 256 + ((u ^ (r & 7)) << 4));
            cp16(base + 32768 + sw, Bhi + (kb + r) * ldb + bn0 + u * 8);
            cp16(base + 49152 + sw, Blo + (kb + r) * ldb + bn0 + u * 8);
        }
        cp_commit();
    };

    float acc[4][4][4];
    #pragma unroll
    for (int i = 0; i < 4; ++i)
        #pragma unroll
        for (int j = 0; j < 4; ++j)
            #pragma unroll
            for (int q = 0; q < 4; ++q) acc[i][j][q] = 0.f;

    load_stage(0, 0);
    load_stage(1, 1);

    const int l16 = lane & 15, l2 = lane >> 4;
    const int bkr  = lane & 15;            // B k-row within k16 slice
    const int bnu0 = (wn * 32) >> 3;       // first 8-col unit of warp's N range

    for (int kt = 0; kt < nk; ++kt){
        if (kt + 2 < nk) load_stage((kt + 2) % 3, kt + 2);
        else cp_commit();                  // keep group count aligned
        cp_wait2();
        __syncthreads();

        const uint32_t sb = sbase + (kt % 3) * STG_BYTES;
        #pragma unroll
        for (int ks = 0; ks < 4; ++ks){    // four k16 slices per k64 stage
            uint32_t aH[4][4], aL[4][4], bH[4][2], bL[4][2];
            #pragma unroll
            for (int mt = 0; mt < 4; ++mt){
                int mr = wm * 64 + mt * 16 + l16;
                uint32_t ad = sb + mr * 128 + (((ks * 2 + l2) ^ (mr & 7)) << 4);
                ldsm_x4(aH[mt][0], aH[mt][1], aH[mt][2], aH[mt][3], ad);
                ldsm_x4(aL[mt][0], aL[mt][1], aL[mt][2], aL[mt][3], ad + 16384);
            }
            #pragma unroll
            for (int p = 0; p < 2; ++p){   // two n16 sub-tiles of warp's n32
                int kr = ks * 16 + bkr;
                int nu = bnu0 + p * 2 + l2;
                uint32_t ad = sb + 32768 + kr * 256 + ((nu ^ (kr & 7)) << 4);
                ldsm_x4_t(bH[2*p][0], bH[2*p][1], bH[2*p+1][0], bH[2*p+1][1], ad);
                ldsm_x4_t(bL[2*p][0], bL[2*p][1], bL[2*p+1][0], bL[2*p+1][1], ad + 16384);
            }
            #pragma unroll
            for (int mt = 0; mt < 4; ++mt)
                #pragma unroll
                for (int nt = 0; nt < 4; ++nt){
                    mma16816(acc[mt][nt], aH[mt][0], aH[mt][1], aH[mt][2], aH[mt][3],
                             bH[nt][0], bH[nt][1]);
                    mma16816(acc[mt][nt], aH[mt][0], aH[mt][1], aH[mt][2], aH[mt][3],
                             bL[nt][0], bL[nt][1]);
                    mma16816(acc[mt][nt], aL[mt][0], aL[mt][1], aL[mt][2], aL[mt][3],
                             bH[nt][0], bH[nt][1]);
                }
        }
        __syncthreads();
    }

    // epilogue: d-frag lane = g*4+q; c0,c1 at (row g, col 2q), c2,c3 at row g+8
    const int g  = lane >> 2;
    const int cp = (lane & 3) * 2;
    if (EPI == 1){
        const float al = *alphap;
        #pragma unroll
        for (int mt = 0; mt < 4; ++mt){
            #pragma unroll
            for (int nt = 0; nt < 4; ++nt){
                long n  = bn0 + wn * 32 + nt * 8 + cp;
                int  nc = (int)(n & 511);
                float b0 = bias[nc], b1 = bias[nc + 1];
                float* C = (n < 512) ? C0 : C1;
                #pragma unroll
                for (int h = 0; h < 2; ++h){
                    long m = arow + wm * 64 + mt * 16 + g + h * 8;
                    float v0 = acc[mt][nt][2*h + 0] + b0;
                    float v1 = acc[mt][nt][2*h + 1] + b1;
                    v0 = (v0 >= 0.f) ? v0 : al * v0;
                    v1 = (v1 >= 0.f) ? v1 : al * v1;
                    *(float2*)&C[m * 512 + nc] = make_float2(v0, v1);
                    if (Hhi){
                        __nv_bfloat16 h0 = __float2bfloat16_rn(v0);
                        __nv_bfloat16 h1 = __float2bfloat16_rn(v1);
                        __nv_bfloat16 q0 = __float2bfloat16_rn(v0 - __bfloat162float(h0));
                        __nv_bfloat16 q1 = __float2bfloat16_rn(v1 - __bfloat162float(h1));
                        *(__nv_bfloat162*)&Hhi[m * 1024 + n] = __halves2bfloat162(h0, h1);
                        *(__nv_bfloat162*)&Hlo[m * 1024 + n] = __halves2bfloat162(q0, q1);
                    }
                }
            }
        }
    } else {
        #pragma unroll
        for (int mt = 0; mt < 4; ++mt){
            #pragma unroll
            for (int nt = 0; nt < 4; ++nt){
                long n = fcol + bn0 + wn * 32 + nt * 8 + cp;
                #pragma unroll
                for (int h = 0; h < 2; ++h){
                    long m = arow + wm * 64 + mt * 16 + g + h * 8;
                    float v0 = acc[mt][nt][2*h + 0];
                    float v1 = acc[mt][nt][2*h + 1];
                    __nv_bfloat16 h0 = __float2bfloat16_rn(v0);
                    __nv_bfloat16 h1 = __float2bfloat16_rn(v1);
                    __nv_bfloat16 q0 = __float2bfloat16_rn(v0 - __bfloat162float(h0));
                    __nv_bfloat16 q1 = __float2bfloat16_rn(v1 - __bfloat162float(h1));
                    *(__nv_bfloat162*)&Fhi[m * 1024 + n] = __halves2bfloat162(h0, h1);
                    *(__nv_bfloat162*)&Flo[m * 1024 + n] = __halves2bfloat162(q0, q1);
                }
            }
        }
    }
}

extern "C" void kernel_launch(void* const* d_in, const int* in_sizes, int n_in,
                              void* d_out, int out_size)
{
    const float* seq_pos = (const float*)d_in[0];
    const float* seq_neg = (const float*)d_in[1];
    const float* adj     = (const float*)d_in[2];
    const float* diff    = (const float*)d_in[3];
    const float* W1a = (const float*)d_in[4];
    const float* W1d = (const float*)d_in[5];
    const float* W2a = (const float*)d_in[6];
    const float* W2d = (const float*)d_in[7];
    const float* b1a = (const float*)d_in[8];
    const float* b1d = (const float*)d_in[9];
    const float* b2a = (const float*)d_in[10];
    const float* b2d = (const float*)d_in[11];
    const float* al1a = (const float*)d_in[12];
    const float* al1d = (const float*)d_in[13];
    const float* al2a = (const float*)d_in[14];
    const float* al2d = (const float*)d_in[15];

    float* out = (float*)d_out;
    const size_t CHN = (size_t)8192 * 512;

    __nv_bfloat16 *adjHi,*adjLo,*difHi,*difLo,*spHi,*spLo,*snHi,*snLo;
    __nv_bfloat16 *wHi,*wLo,*ftAHi,*ftALo,*ftDHi,*ftDLo,*hAHi,*hALo,*hDHi,*hDLo;
    cudaGetSymbolAddress((void**)&adjHi, g_adjHi);
    cudaGetSymbolAddress((void**)&adjLo, g_adjLo);
    cudaGetSymbolAddress((void**)&difHi, g_difHi);
    cudaGetSymbolAddress((void**)&difLo, g_difLo);
    cudaGetSymbolAddress((void**)&spHi,  g_spHi);
    cudaGetSymbolAddress((void**)&spLo,  g_spLo);
    cudaGetSymbolAddress((void**)&snHi,  g_snHi);
    cudaGetSymbolAddress((void**)&snLo,  g_snLo);
    cudaGetSymbolAddress((void**)&wHi,   g_wHi);
    cudaGetSymbolAddress((void**)&wLo,   g_wLo);
    cudaGetSymbolAddress((void**)&ftAHi, g_ftAHi);
    cudaGetSymbolAddress((void**)&ftALo, g_ftALo);
    cudaGetSymbolAddress((void**)&ftDHi, g_ftDHi);
    cudaGetSymbolAddress((void**)&ftDLo, g_ftDLo);
    cudaGetSymbolAddress((void**)&hAHi,  g_hAHi);
    cudaGetSymbolAddress((void**)&hALo,  g_hALo);
    cudaGetSymbolAddress((void**)&hDHi,  g_hDHi);
    cudaGetSymbolAddress((void**)&hDLo,  g_hDLo);

    cudaFuncSetAttribute(gemm_mma<0>, cudaFuncAttributeMaxDynamicSharedMemorySize, SMEM_DYN);
    cudaFuncSetAttribute(gemm_mma<1>, cudaFuncAttributeMaxDynamicSharedMemorySize, SMEM_DYN);

    // bf16 hi/lo splits (W is [in,out] = [K,N] already; no transpose needed)
    split_k<<<65536, 256>>>(adj,  adjHi, adjLo, NEL_ADJ);
    split_k<<<65536, 256>>>(diff, difHi, difLo, NEL_ADJ);
    split_k<<<4096,  256>>>(seq_pos, spHi, spLo, NEL_SEQ);
    split_k<<<4096,  256>>>(seq_neg, snHi, snLo, NEL_SEQ);
    split_k<<<256,   256>>>(W1a, wHi + 0*NEL_W, wLo + 0*NEL_W, NEL_W);
    split_k<<<256,   256>>>(W1d, wHi + 1*NEL_W, wLo + 1*NEL_W, NEL_W);
    split_k<<<256,   256>>>(W2a, wHi + 2*NEL_W, wLo + 2*NEL_W, NEL_W);
    split_k<<<256,   256>>>(W2d, wHi + 3*NEL_W, wLo + 3*NEL_W, NEL_W);

    dim3 blk(256);
    dim3 gS(4, 64);   // N=512 small gemm (128-wide N tiles)
    dim3 gB(8, 64);   // N=1024 big gemm

    // layer 1 small: fts[k][n] = seq @ W1 (pos cols 0-511, neg 512-1023)
    gemm_mma<0><<<gS, blk, SMEM_DYN>>>(spHi, spLo, 512, 0, wHi+0*NEL_W, wLo+0*NEL_W, 512, 512,
        ftAHi, ftALo, 0,   nullptr,nullptr,nullptr,nullptr,nullptr,nullptr);
    gemm_mma<0><<<gS, blk, SMEM_DYN>>>(snHi, snLo, 512, 0, wHi+0*NEL_W, wLo+0*NEL_W, 512, 512,
        ftAHi, ftALo, 512, nullptr,nullptr,nullptr,nullptr,nullptr,nullptr);
    gemm_mma<0><<<gS, blk, SMEM_DYN>>>(spHi, spLo, 512, 0, wHi+1*NEL_W, wLo+1*NEL_W, 512, 512,
        ftDHi, ftDLo, 0,   nullptr,nullptr,nullptr,nullptr,nullptr,nullptr);
    gemm_mma<0><<<gS, blk, SMEM_DYN>>>(snHi, snLo, 512, 0, wHi+1*NEL_W, wLo+1*NEL_W, 512, 512,
        ftDHi, ftDLo, 512, nullptr,nullptr,nullptr,nullptr,nullptr,nullptr);

    // layer 1 big: h1 = prelu(A @ fts + b); also emit h1 bf16 hi/lo
    gemm_mma<1><<<gB, blk, SMEM_DYN>>>(adjHi, adjLo, 8192, 0, ftAHi, ftALo, 1024, 8192,
        nullptr,nullptr,0, out + 0*CHN, out + 4*CHN, b1a, al1a, hAHi, hALo);
    gemm_mma<1><<<gB, blk, SMEM_DYN>>>(difHi, difLo, 8192, 0, ftDHi, ftDLo, 1024, 8192,
        nullptr,nullptr,0, out + 1*CHN, out + 5*CHN, b1d, al1d, hDHi, hDLo);

    // layer 2 small: fts2 = h1 @ W2
    gemm_mma<0><<<gS, blk, SMEM_DYN>>>(hAHi, hALo, 1024, 0,   wHi+2*NEL_W, wLo+2*NEL_W, 512, 512,
        ftAHi, ftALo, 0,   nullptr,nullptr,nullptr,nullptr,nullptr,nullptr);
    gemm_mma<0><<<gS, blk, SMEM_DYN>>>(hAHi, hALo, 1024, 512, wHi+2*NEL_W, wLo+2*NEL_W, 512, 512,
        ftAHi, ftALo, 512, nullptr,nullptr,nullptr,nullptr,nullptr,nullptr);
    gemm_mma<0><<<gS, blk, SMEM_DYN>>>(hDHi, hDLo, 1024, 0,   wHi+3*NEL_W, wLo+3*NEL_W, 512, 512,
        ftDHi, ftDLo, 0,   nullptr,nullptr,nullptr,nullptr,nullptr,nullptr);
    gemm_mma<0><<<gS, blk, SMEM_DYN>>>(hDHi, hDLo, 1024, 512, wHi+3*NEL_W, wLo+3*NEL_W, 512, 512,
        ftDHi, ftDLo, 512, nullptr,nullptr,nullptr,nullptr,nullptr,nullptr);

    // layer 2 big
    gemm_mma<1><<<gB, blk, SMEM_DYN>>>(adjHi, adjLo, 8192, 0, ftAHi, ftALo, 1024, 8192,
        nullptr,nullptr,0, out + 2*CHN, out + 6*CHN, b2a, al2a, nullptr, nullptr);
    gemm_mma<1><<<gB, blk, SMEM_DYN>>>(difHi, difLo, 8192, 0, ftDHi, ftDLo, 1024, 8192,
        nullptr,nullptr,0, out + 3*CHN, out + 7*CHN, b2d, al2d, nullptr, nullptr);
}

// round 9
// speedup vs baseline: 3.5379x; 1.0257x over previous
#include <cuda_runtime.h>
#include <cuda_bf16.h>
#include <stdint.h>

// Model_63256278335531: 2-layer dual-GCN via bf16x3 mma.sync (HMMA) GEMMs.
// D = Ah*Bh + Ah*Bl + Al*Bh (fp32 register accumulate) ~ fp32-accurate.

#define NEL_ADJ (8192ull*8192ull)
#define NEL_SEQ (8192ull*512ull)
#define NEL_W   (512ull*512ull)
#define NEL_FTS (8192ull*1024ull)

__device__ __align__(16) __nv_bfloat16 g_adjHi[NEL_ADJ];
__device__ __align__(16) __nv_bfloat16 g_adjLo[NEL_ADJ];
__device__ __align__(16) __nv_bfloat16 g_difHi[NEL_ADJ];
__device__ __align__(16) __nv_bfloat16 g_difLo[NEL_ADJ];
__device__ __align__(16) __nv_bfloat16 g_spHi[NEL_SEQ], g_spLo[NEL_SEQ];
__device__ __align__(16) __nv_bfloat16 g_snHi[NEL_SEQ], g_snLo[NEL_SEQ];
__device__ __align__(16) __nv_bfloat16 g_wHi[4][NEL_W], g_wLo[4][NEL_W];
// fts as B operand of big GEMM: [K=8192][N=1024] (pos cols 0-511, neg 512-1023)
__device__ __align__(16) __nv_bfloat16 g_ftAHi[NEL_FTS], g_ftALo[NEL_FTS];
__device__ __align__(16) __nv_bfloat16 g_ftDHi[NEL_FTS], g_ftDLo[NEL_FTS];
// h1 packed [M=8192][1024]: A operand for layer-2 small GEMM
__device__ __align__(16) __nv_bfloat16 g_hAHi[NEL_FTS], g_hALo[NEL_FTS];
__device__ __align__(16) __nv_bfloat16 g_hDHi[NEL_FTS], g_hDLo[NEL_FTS];

__device__ __forceinline__ uint32_t smem_u32(const void* p){
    uint32_t a;
    asm("{ .reg .u64 t; cvta.to.shared.u64 t, %1; cvt.u32.u64 %0, t; }"
        : "=r"(a) : "l"(p));
    return a;
}
__device__ __forceinline__ void cp16(uint32_t dst, const void* src){
    asm volatile("{ .reg .u64 g; cvta.to.global.u64 g, %1;"
                 " cp.async.cg.shared.global [%0], [g], 16; }"
                 :: "r"(dst), "l"(src) : "memory");
}
__device__ __forceinline__ void cp_commit(){
    asm volatile("cp.async.commit_group;" ::: "memory");
}
__device__ __forceinline__ void cp_wait1(){
    asm volatile("cp.async.wait_group 1;" ::: "memory");
}
__device__ __forceinline__ void ldsm_x4(uint32_t& r0, uint32_t& r1,
                                        uint32_t& r2, uint32_t& r3, uint32_t a){
    asm volatile("ldmatrix.sync.aligned.m8n8.x4.shared.b16 {%0,%1,%2,%3}, [%4];"
                 : "=r"(r0), "=r"(r1), "=r"(r2), "=r"(r3) : "r"(a));
}
__device__ __forceinline__ void ldsm_x4_t(uint32_t& r0, uint32_t& r1,
                                          uint32_t& r2, uint32_t& r3, uint32_t a){
    asm volatile("ldmatrix.sync.aligned.m8n8.x4.trans.shared.b16 {%0,%1,%2,%3}, [%4];"
                 : "=r"(r0), "=r"(r1), "=r"(r2), "=r"(r3) : "r"(a));
}
__device__ __forceinline__ void mma16816(float* c, uint32_t a0, uint32_t a1,
                                         uint32_t a2, uint32_t a3,
                                         uint32_t b0, uint32_t b1){
    asm volatile("mma.sync.aligned.m16n8k16.row.col.f32.bf16.bf16.f32 "
                 "{%0,%1,%2,%3}, {%4,%5,%6,%7}, {%8,%9}, {%0,%1,%2,%3};"
                 : "+f"(c[0]), "+f"(c[1]), "+f"(c[2]), "+f"(c[3])
                 : "r"(a0), "r"(a1), "r"(a2), "r"(a3), "r"(b0), "r"(b1));
}

// ---- fused hi/lo split over all inputs (one launch) ------------------------
__device__ __forceinline__ void split4(const float* __restrict__ x,
                                       __nv_bfloat16* __restrict__ hi,
                                       __nv_bfloat16* __restrict__ lo, size_t i)
{
    float4 v = *(const float4*)(x + i);
    __nv_bfloat16 h0 = __float2bfloat16_rn(v.x), h1 = __float2bfloat16_rn(v.y);
    __nv_bfloat16 h2 = __float2bfloat16_rn(v.z), h3 = __float2bfloat16_rn(v.w);
    __nv_bfloat16 l0 = __float2bfloat16_rn(v.x - __bfloat162float(h0));
    __nv_bfloat16 l1 = __float2bfloat16_rn(v.y - __bfloat162float(h1));
    __nv_bfloat16 l2 = __float2bfloat16_rn(v.z - __bfloat162float(h2));
    __nv_bfloat16 l3 = __float2bfloat16_rn(v.w - __bfloat162float(h3));
    __nv_bfloat162* H = (__nv_bfloat162*)(hi + i);
    H[0] = __halves2bfloat162(h0, h1); H[1] = __halves2bfloat162(h2, h3);
    __nv_bfloat162* L = (__nv_bfloat162*)(lo + i);
    L[0] = __halves2bfloat162(l0, l1); L[1] = __halves2bfloat162(l2, l3);
}

__global__ void fused_split(const float* __restrict__ adj, const float* __restrict__ dif,
                            const float* __restrict__ sp,  const float* __restrict__ sn,
                            const float* __restrict__ w0,  const float* __restrict__ w1,
                            const float* __restrict__ w2,  const float* __restrict__ w3,
                            __nv_bfloat16* adjHi, __nv_bfloat16* adjLo,
                            __nv_bfloat16* difHi, __nv_bfloat16* difLo,
                            __nv_bfloat16* spHi,  __nv_bfloat16* spLo,
                            __nv_bfloat16* snHi,  __nv_bfloat16* snLo,
                            __nv_bfloat16* wHi,   __nv_bfloat16* wLo)
{
    size_t o = ((size_t)blockIdx.x * blockDim.x + threadIdx.x) * 4;
    if (o < NEL_ADJ) { split4(adj, adjHi, adjLo, o); return; } o -= NEL_ADJ;
    if (o < NEL_ADJ) { split4(dif, difHi, difLo, o); return; } o -= NEL_ADJ;
    if (o < NEL_SEQ) { split4(sp,  spHi,  spLo,  o); return; } o -= NEL_SEQ;
    if (o < NEL_SEQ) { split4(sn,  snHi,  snLo,  o); return; } o -= NEL_SEQ;
    if (o < NEL_W) { split4(w0, wHi + 0*NEL_W, wLo + 0*NEL_W, o); return; } o -= NEL_W;
    if (o < NEL_W) { split4(w1, wHi + 1*NEL_W, wLo + 1*NEL_W, o); return; } o -= NEL_W;
    if (o < NEL_W) { split4(w2, wHi + 2*NEL_W, wLo + 2*NEL_W, o); return; } o -= NEL_W;
    if (o < NEL_W) { split4(w3, wHi + 3*NEL_W, wLo + 3*NEL_W, o); }
}

// CTA 128(M) x 128(N), K-stage 64, 3-stage cp.async pipeline, 1 sync/iter.
// 8 warps: wm = wid&1 (M-halves of 64), wn = wid>>1 (N-quarters of 32).
// Stage layout: AH[128][64] AL BH[64][128] BL = 16KB each, 64KB/stage.
// A rows 128B (8x16B units), swizzle unit u -> u ^ (row&7).
// B rows 256B (16x16B units), same low-3-bit XOR swizzle.
// EPI=0: acc -> bf16 hi/lo into F[m*1024 + fcol + n]   (fts path, m is k-row)
// EPI=1: v = prelu(acc + bias[n&511]); fp32 -> (n<512?C0:C1)[m*512+(n&511)];
//        optional bf16 hi/lo h1 at H[m*1024+n].
#define STG_BYTES 65536
#define SMEM_DYN  (3*STG_BYTES)

template<int EPI>
__global__ void __launch_bounds__(256, 1)
gemm_mma(const __nv_bfloat16* __restrict__ Ahi, const __nv_bfloat16* __restrict__ Alo,
         long lda, long aofs,
         const __nv_bfloat16* __restrict__ Bhi, const __nv_bfloat16* __restrict__ Blo,
         long ldb, int K,
         __nv_bfloat16* __restrict__ Fhi, __nv_bfloat16* __restrict__ Flo, long fcol,
         float* __restrict__ C0, float* __restrict__ C1,
         const float* __restrict__ bias, const float* __restrict__ alphap,
         __nv_bfloat16* __restrict__ Hhi, __nv_bfloat16* __restrict__ Hlo)
{
    extern __shared__ __align__(1024) char smem[];
    const uint32_t sbase = smem_u32(smem);

    const int tid  = threadIdx.x;
    const int lane = tid & 31;
    const int wid  = tid >> 5;
    const int wm   = wid & 1;
    const int wn   = wid >> 1;
    const long arow = (long)blockIdx.y * 128;
    const long bn0  = (long)blockIdx.x * 128;
    const int  nk   = K >> 6;

    auto load_stage = [&](int st, int kc){
        uint32_t base = sbase + st * STG_BYTES;
        const long ka = aofs + (long)kc * 64;
        const long kb = (long)kc * 64;
        #pragma unroll
        for (int s = 0; s < 4; ++s){
            int idx = tid + 256 * s;
            int r = idx >> 3, u = idx & 7;      // A: 128 rows x 8 units
            uint32_t sw = (uint32_t)(r * 128 + ((u ^ (r & 7)) << 4));
            cp16(base + sw,         Ahi + (arow + r) * lda + ka + u * 8);
            cp16(base + 16384 + sw, Alo + (arow + r) * lda + ka + u * 8);
        }
        #pragma unroll
        for (int s = 0; s < 4; ++s){
            int idx = tid + 256 * s;
            int r = idx >> 4, u = idx & 15;     // B: 64 rows x 16 units
            uint32_t sw = (uint32_t)(r * 256 + ((u ^ (r & 7)) << 4));
            cp16(base + 32768 + sw, Bhi + (kb + r) * ldb + bn0 + u * 8);
            cp16(base + 49152 + sw, Blo + (kb + r) * ldb + bn0 + u * 8);
        }
        cp_commit();
    };

    float acc[4][4][4];
    #pragma unroll
    for (int i = 0; i < 4; ++i)
        #pragma unroll
        for (int j = 0; j < 4; ++j)
            #pragma unroll
            for (int q = 0; q < 4; ++q) acc[i][j][q] = 0.f;

    load_stage(0, 0);
    load_stage(1, 1);

    const int l16 = lane & 15, l2 = lane >> 4;
    const int bkr  = lane & 15;            // B k-row within k16 slice
    const int bnu0 = (wn * 32) >> 3;       // first 8-col unit of warp's N range

    for (int kt = 0; kt < nk; ++kt){
        cp_wait1();                 // stage kt's copies (this thread) done
        __syncthreads();            // all threads' copies done; stage kt-1 fully consumed
        if (kt + 2 < nk) load_stage((kt + 2) % 3, kt + 2);  // overwrites stage kt-1
        else cp_commit();           // keep group accounting aligned

        const uint32_t sb = sbase + (kt % 3) * STG_BYTES;
        #pragma unroll
        for (int ks = 0; ks < 4; ++ks){    // four k16 slices per k64 stage
            uint32_t aH[4][4], aL[4][4], bH[4][2], bL[4][2];
            #pragma unroll
            for (int mt = 0; mt < 4; ++mt){
                int mr = wm * 64 + mt * 16 + l16;
                uint32_t ad = sb + mr * 128 + (((ks * 2 + l2) ^ (mr & 7)) << 4);
                ldsm_x4(aH[mt][0], aH[mt][1], aH[mt][2], aH[mt][3], ad);
                ldsm_x4(aL[mt][0], aL[mt][1], aL[mt][2], aL[mt][3], ad + 16384);
            }
            #pragma unroll
            for (int p = 0; p < 2; ++p){   // two n16 sub-tiles of warp's n32
                int kr = ks * 16 + bkr;
                int nu = bnu0 + p * 2 + l2;
                uint32_t ad = sb + 32768 + kr * 256 + ((nu ^ (kr & 7)) << 4);
                ldsm_x4_t(bH[2*p][0], bH[2*p][1], bH[2*p+1][0], bH[2*p+1][1], ad);
                ldsm_x4_t(bL[2*p][0], bL[2*p][1], bL[2*p+1][0], bL[2*p+1][1], ad + 16384);
            }
            #pragma unroll
            for (int mt = 0; mt < 4; ++mt)
                #pragma unroll
                for (int nt = 0; nt < 4; ++nt){
                    mma16816(acc[mt][nt], aH[mt][0], aH[mt][1], aH[mt][2], aH[mt][3],
                             bH[nt][0], bH[nt][1]);
                    mma16816(acc[mt][nt], aH[mt][0], aH[mt][1], aH[mt][2], aH[mt][3],
                             bL[nt][0], bL[nt][1]);
                    mma16816(acc[mt][nt], aL[mt][0], aL[mt][1], aL[mt][2], aL[mt][3],
                             bH[nt][0], bH[nt][1]);
                }
        }
    }

    // epilogue: d-frag lane = g*4+q; c0,c1 at (row g, col 2q), c2,c3 at row g+8
    const int g  = lane >> 2;
    const int cp = (lane & 3) * 2;
    if (EPI == 1){
        const float al = *alphap;
        #pragma unroll
        for (int mt = 0; mt < 4; ++mt){
            #pragma unroll
            for (int nt = 0; nt < 4; ++nt){
                long n  = bn0 + wn * 32 + nt * 8 + cp;
                int  nc = (int)(n & 511);
                float b0 = bias[nc], b1 = bias[nc + 1];
                float* C = (n < 512) ? C0 : C1;
                #pragma unroll
                for (int h = 0; h < 2; ++h){
                    long m = arow + wm * 64 + mt * 16 + g + h * 8;
                    float v0 = acc[mt][nt][2*h + 0] + b0;
                    float v1 = acc[mt][nt][2*h + 1] + b1;
                    v0 = (v0 >= 0.f) ? v0 : al * v0;
                    v1 = (v1 >= 0.f) ? v1 : al * v1;
                    *(float2*)&C[m * 512 + nc] = make_float2(v0, v1);
                    if (Hhi){
                        __nv_bfloat16 h0 = __float2bfloat16_rn(v0);
                        __nv_bfloat16 h1 = __float2bfloat16_rn(v1);
                        __nv_bfloat16 q0 = __float2bfloat16_rn(v0 - __bfloat162float(h0));
                        __nv_bfloat16 q1 = __float2bfloat16_rn(v1 - __bfloat162float(h1));
                        *(__nv_bfloat162*)&Hhi[m * 1024 + n] = __halves2bfloat162(h0, h1);
                        *(__nv_bfloat162*)&Hlo[m * 1024 + n] = __halves2bfloat162(q0, q1);
                    }
                }
            }
        }
    } else {
        #pragma unroll
        for (int mt = 0; mt < 4; ++mt){
            #pragma unroll
            for (int nt = 0; nt < 4; ++nt){
                long n = fcol + bn0 + wn * 32 + nt * 8 + cp;
                #pragma unroll
                for (int h = 0; h < 2; ++h){
                    long m = arow + wm * 64 + mt * 16 + g + h * 8;
                    float v0 = acc[mt][nt][2*h + 0];
                    float v1 = acc[mt][nt][2*h + 1];
                    __nv_bfloat16 h0 = __float2bfloat16_rn(v0);
                    __nv_bfloat16 h1 = __float2bfloat16_rn(v1);
                    __nv_bfloat16 q0 = __float2bfloat16_rn(v0 - __bfloat162float(h0));
                    __nv_bfloat16 q1 = __float2bfloat16_rn(v1 - __bfloat162float(h1));
                    *(__nv_bfloat162*)&Fhi[m * 1024 + n] = __halves2bfloat162(h0, h1);
                    *(__nv_bfloat162*)&Flo[m * 1024 + n] = __halves2bfloat162(q0, q1);
                }
            }
        }
    }
}

extern "C" void kernel_launch(void* const* d_in, const int* in_sizes, int n_in,
                              void* d_out, int out_size)
{
    const float* seq_pos = (const float*)d_in[0];
    const float* seq_neg = (const float*)d_in[1];
    const float* adj     = (const float*)d_in[2];
    const float* diff    = (const float*)d_in[3];
    const float* W1a = (const float*)d_in[4];
    const float* W1d = (const float*)d_in[5];
    const float* W2a = (const float*)d_in[6];
    const float* W2d = (const float*)d_in[7];
    const float* b1a = (const float*)d_in[8];
    const float* b1d = (const float*)d_in[9];
    const float* b2a = (const float*)d_in[10];
    const float* b2d = (const float*)d_in[11];
    const float* al1a = (const float*)d_in[12];
    const float* al1d = (const float*)d_in[13];
    const float* al2a = (const float*)d_in[14];
    const float* al2d = (const float*)d_in[15];

    float* out = (float*)d_out;
    const size_t CHN = (size_t)8192 * 512;

    __nv_bfloat16 *adjHi,*adjLo,*difHi,*difLo,*spHi,*spLo,*snHi,*snLo;
    __nv_bfloat16 *wHi,*wLo,*ftAHi,*ftALo,*ftDHi,*ftDLo,*hAHi,*hALo,*hDHi,*hDLo;
    cudaGetSymbolAddress((void**)&adjHi, g_adjHi);
    cudaGetSymbolAddress((void**)&adjLo, g_adjLo);
    cudaGetSymbolAddress((void**)&difHi, g_difHi);
    cudaGetSymbolAddress((void**)&difLo, g_difLo);
    cudaGetSymbolAddress((void**)&spHi,  g_spHi);
    cudaGetSymbolAddress((void**)&spLo,  g_spLo);
    cudaGetSymbolAddress((void**)&snHi,  g_snHi);
    cudaGetSymbolAddress((void**)&snLo,  g_snLo);
    cudaGetSymbolAddress((void**)&wHi,   g_wHi);
    cudaGetSymbolAddress((void**)&wLo,   g_wLo);
    cudaGetSymbolAddress((void**)&ftAHi, g_ftAHi);
    cudaGetSymbolAddress((void**)&ftALo, g_ftALo);
    cudaGetSymbolAddress((void**)&ftDHi, g_ftDHi);
    cudaGetSymbolAddress((void**)&ftDLo, g_ftDLo);
    cudaGetSymbolAddress((void**)&hAHi,  g_hAHi);
    cudaGetSymbolAddress((void**)&hALo,  g_hALo);
    cudaGetSymbolAddress((void**)&hDHi,  g_hDHi);
    cudaGetSymbolAddress((void**)&hDLo,  g_hDLo);

    cudaFuncSetAttribute(gemm_mma<0>, cudaFuncAttributeMaxDynamicSharedMemorySize, SMEM_DYN);
    cudaFuncSetAttribute(gemm_mma<1>, cudaFuncAttributeMaxDynamicSharedMemorySize, SMEM_DYN);

    // one fused conversion launch for all hi/lo splits
    {
        size_t total_vec4 = (2*NEL_ADJ + 2*NEL_SEQ + 4*NEL_W) / 4;
        int blocks = (int)((total_vec4 + 255) / 256);
        fused_split<<<blocks, 256>>>(adj, diff, seq_pos, seq_neg, W1a, W1d, W2a, W2d,
                                     adjHi, adjLo, difHi, difLo,
                                     spHi, spLo, snHi, snLo, wHi, wLo);
    }

    dim3 blk(256);
    dim3 gS(4, 64);   // N=512 small gemm (128-wide N tiles)
    dim3 gB(8, 64);   // N=1024 big gemm

    // layer 1 small: fts[k][n] = seq @ W1 (pos cols 0-511, neg 512-1023)
    gemm_mma<0><<<gS, blk, SMEM_DYN>>>(spHi, spLo, 512, 0, wHi+0*NEL_W, wLo+0*NEL_W, 512, 512,
        ftAHi, ftALo, 0,   nullptr,nullptr,nullptr,nullptr,nullptr,nullptr);
    gemm_mma<0><<<gS, blk, SMEM_DYN>>>(snHi, snLo, 512, 0, wHi+0*NEL_W, wLo+0*NEL_W, 512, 512,
        ftAHi, ftALo, 512, nullptr,nullptr,nullptr,nullptr,nullptr,nullptr);
    gemm_mma<0><<<gS, blk, SMEM_DYN>>>(spHi, spLo, 512, 0, wHi+1*NEL_W, wLo+1*NEL_W, 512, 512,
        ftDHi, ftDLo, 0,   nullptr,nullptr,nullptr,nullptr,nullptr,nullptr);
    gemm_mma<0><<<gS, blk, SMEM_DYN>>>(snHi, snLo, 512, 0, wHi+1*NEL_W, wLo+1*NEL_W, 512, 512,
        ftDHi, ftDLo, 512, nullptr,nullptr,nullptr,nullptr,nullptr,nullptr);

    // layer 1 big: h1 = prelu(A @ fts + b); also emit h1 bf16 hi/lo
    gemm_mma<1><<<gB, blk, SMEM_DYN>>>(adjHi, adjLo, 8192, 0, ftAHi, ftALo, 1024, 8192,
        nullptr,nullptr,0, out + 0*CHN, out + 4*CHN, b1a, al1a, hAHi, hALo);
    gemm_mma<1><<<gB, blk, SMEM_DYN>>>(difHi, difLo, 8192, 0, ftDHi, ftDLo, 1024, 8192,
        nullptr,nullptr,0, out + 1*CHN, out + 5*CHN, b1d, al1d, hDHi, hDLo);

    // layer 2 small: fts2 = h1 @ W2
    gemm_mma<0><<<gS, blk, SMEM_DYN>>>(hAHi, hALo, 1024, 0,   wHi+2*NEL_W, wLo+2*NEL_W, 512, 512,
        ftAHi, ftALo, 0,   nullptr,nullptr,nullptr,nullptr,nullptr,nullptr);
    gemm_mma<0><<<gS, blk, SMEM_DYN>>>(hAHi, hALo, 1024, 512, wHi+2*NEL_W, wLo+2*NEL_W, 512, 512,
        ftAHi, ftALo, 512, nullptr,nullptr,nullptr,nullptr,nullptr,nullptr);
    gemm_mma<0><<<gS, blk, SMEM_DYN>>>(hDHi, hDLo, 1024, 0,   wHi+3*NEL_W, wLo+3*NEL_W, 512, 512,
        ftDHi, ftDLo, 0,   nullptr,nullptr,nullptr,nullptr,nullptr,nullptr);
    gemm_mma<0><<<gS, blk, SMEM_DYN>>>(hDHi, hDLo, 1024, 512, wHi+3*NEL_W, wLo+3*NEL_W, 512, 512,
        ftDHi, ftDLo, 512, nullptr,nullptr,nullptr,nullptr,nullptr,nullptr);

    // layer 2 big
    gemm_mma<1><<<gB, blk, SMEM_DYN>>>(adjHi, adjLo, 8192, 0, ftAHi, ftALo, 1024, 8192,
        nullptr,nullptr,0, out + 2*CHN, out + 6*CHN, b2a, al2a, nullptr, nullptr);
    gemm_mma<1><<<gB, blk, SMEM_DYN>>>(difHi, difLo, 8192, 0, ftDHi, ftDLo, 1024, 8192,
        nullptr,nullptr,0, out + 3*CHN, out + 7*CHN, b2d, al2d, nullptr, nullptr);
}

// round 10
// speedup vs baseline: 5.7622x; 1.6287x over previous
#include <cuda_runtime.h>
#include <cuda_fp16.h>
#include <stdint.h>

// Model_63256278335531: 2-layer dual-GCN via fp16x2 mma.sync (HMMA) GEMMs.
// Big GEMM:   D = Ah*Bh + Ah*Bl   (A = adj/diff hi-only, B = fts hi+lo)
// Small GEMM: D = Ah*Bh + Al*Bh   (A = seq/h1 hi+lo,     B = W hi-only)
// fp32 register accumulate; fp16 11-bit mantissa keeps rel_err ~2e-4.

#define NEL_ADJ (8192ull*8192ull)
#define NEL_SEQ (8192ull*512ull)
#define NEL_W   (512ull*512ull)
#define NEL_FTS (8192ull*1024ull)

__device__ __align__(16) __half g_adjHi[NEL_ADJ];
__device__ __align__(16) __half g_difHi[NEL_ADJ];
__device__ __align__(16) __half g_spHi[NEL_SEQ], g_spLo[NEL_SEQ];
__device__ __align__(16) __half g_snHi[NEL_SEQ], g_snLo[NEL_SEQ];
__device__ __align__(16) __half g_wHi[4][NEL_W];
// fts as B of big GEMM: [K=8192][N=1024] (pos cols 0-511, neg 512-1023)
__device__ __align__(16) __half g_ftAHi[NEL_FTS], g_ftALo[NEL_FTS];
__device__ __align__(16) __half g_ftDHi[NEL_FTS], g_ftDLo[NEL_FTS];
// h1 packed [M=8192][1024]: A of layer-2 small GEMM
__device__ __align__(16) __half g_hAHi[NEL_FTS], g_hALo[NEL_FTS];
__device__ __align__(16) __half g_hDHi[NEL_FTS], g_hDLo[NEL_FTS];

__device__ __forceinline__ uint32_t smem_u32(const void* p){
    uint32_t a;
    asm("{ .reg .u64 t; cvta.to.shared.u64 t, %1; cvt.u32.u64 %0, t; }"
        : "=r"(a) : "l"(p));
    return a;
}
__device__ __forceinline__ void cp16(uint32_t dst, const void* src){
    asm volatile("{ .reg .u64 g; cvta.to.global.u64 g, %1;"
                 " cp.async.cg.shared.global [%0], [g], 16; }"
                 :: "r"(dst), "l"(src) : "memory");
}
__device__ __forceinline__ void cp_commit(){
    asm volatile("cp.async.commit_group;" ::: "memory");
}
__device__ __forceinline__ void cp_wait1(){
    asm volatile("cp.async.wait_group 1;" ::: "memory");
}
__device__ __forceinline__ void ldsm_x4(uint32_t& r0, uint32_t& r1,
                                        uint32_t& r2, uint32_t& r3, uint32_t a){
    asm volatile("ldmatrix.sync.aligned.m8n8.x4.shared.b16 {%0,%1,%2,%3}, [%4];"
                 : "=r"(r0), "=r"(r1), "=r"(r2), "=r"(r3) : "r"(a));
}
__device__ __forceinline__ void ldsm_x4_t(uint32_t& r0, uint32_t& r1,
                                          uint32_t& r2, uint32_t& r3, uint32_t a){
    asm volatile("ldmatrix.sync.aligned.m8n8.x4.trans.shared.b16 {%0,%1,%2,%3}, [%4];"
                 : "=r"(r0), "=r"(r1), "=r"(r2), "=r"(r3) : "r"(a));
}
__device__ __forceinline__ void mma16816(float* c, const uint32_t* a,
                                         uint32_t b0, uint32_t b1){
    asm volatile("mma.sync.aligned.m16n8k16.row.col.f32.f16.f16.f32 "
                 "{%0,%1,%2,%3}, {%4,%5,%6,%7}, {%8,%9}, {%0,%1,%2,%3};"
                 : "+f"(c[0]), "+f"(c[1]), "+f"(c[2]), "+f"(c[3])
                 : "r"(a[0]), "r"(a[1]), "r"(a[2]), "r"(a[3]), "r"(b0), "r"(b1));
}

// ---- fused conversion: adj/dif/W -> fp16 hi; seq -> fp16 hi+lo --------------
__device__ __forceinline__ void cv_hi(const float* __restrict__ x,
                                      __half* __restrict__ hi, size_t i)
{
    float4 v = *(const float4*)(x + i);
    __half2* H = (__half2*)(hi + i);
    H[0] = __halves2half2(__float2half_rn(v.x), __float2half_rn(v.y));
    H[1] = __halves2half2(__float2half_rn(v.z), __float2half_rn(v.w));
}
__device__ __forceinline__ void cv_hl(const float* __restrict__ x,
                                      __half* __restrict__ hi,
                                      __half* __restrict__ lo, size_t i)
{
    float4 v = *(const float4*)(x + i);
    __half h0 = __float2half_rn(v.x), h1 = __float2half_rn(v.y);
    __half h2 = __float2half_rn(v.z), h3 = __float2half_rn(v.w);
    __half l0 = __float2half_rn(v.x - __half2float(h0));
    __half l1 = __float2half_rn(v.y - __half2float(h1));
    __half l2 = __float2half_rn(v.z - __half2float(h2));
    __half l3 = __float2half_rn(v.w - __half2float(h3));
    __half2* H = (__half2*)(hi + i);
    H[0] = __halves2half2(h0, h1); H[1] = __halves2half2(h2, h3);
    __half2* L = (__half2*)(lo + i);
    L[0] = __halves2half2(l0, l1); L[1] = __halves2half2(l2, l3);
}

__global__ void fused_split(const float* __restrict__ adj, const float* __restrict__ dif,
                            const float* __restrict__ sp,  const float* __restrict__ sn,
                            const float* __restrict__ w0,  const float* __restrict__ w1,
                            const float* __restrict__ w2,  const float* __restrict__ w3,
                            __half* adjHi, __half* difHi,
                            __half* spHi, __half* spLo,
                            __half* snHi, __half* snLo, __half* wHi)
{
    size_t o = ((size_t)blockIdx.x * blockDim.x + threadIdx.x) * 4;
    if (o < NEL_ADJ) { cv_hi(adj, adjHi, o); return; } o -= NEL_ADJ;
    if (o < NEL_ADJ) { cv_hi(dif, difHi, o); return; } o -= NEL_ADJ;
    if (o < NEL_SEQ) { cv_hl(sp, spHi, spLo, o); return; } o -= NEL_SEQ;
    if (o < NEL_SEQ) { cv_hl(sn, snHi, snLo, o); return; } o -= NEL_SEQ;
    if (o < NEL_W) { cv_hi(w0, wHi + 0*NEL_W, o); return; } o -= NEL_W;
    if (o < NEL_W) { cv_hi(w1, wHi + 1*NEL_W, o); return; } o -= NEL_W;
    if (o < NEL_W) { cv_hi(w2, wHi + 2*NEL_W, o); return; } o -= NEL_W;
    if (o < NEL_W) { cv_hi(w3, wHi + 3*NEL_W, o); }
}

// ---- GEMM core --------------------------------------------------------------
// CTA 128(M) x 128(N), K-stage 64, 3-stage cp.async pipeline, 1 sync/iter.
// 8 warps: wm = wid&1 (M-halves of 64), wn = wid>>1 (N-quarters of 32).
// Stage 48KB. big: AH@0 BH@16K BL@32K.  small: AH@0 AL@16K BH@32K.
// A rows 128B (8x16B units), swizzle unit u -> u ^ (row&7).
// B rows 256B (16x16B units), same low-3-bit XOR swizzle.
#define STG_BYTES 49152
#define SMEM_DYN  (3*STG_BYTES)

struct SmallArgs {
    const __half* Ahi[4]; const __half* Alo[4];
    long lda[4]; long aofs[4];
    const __half* Bhi[4];
    __half* Fhi[4]; __half* Flo[4];
    long fcol[4];
};
struct BigArgs {
    const __half* Ahi[2];
    const __half* Bhi[2]; const __half* Blo[2];
    float* C0[2]; float* C1[2];
    const float* bias[2]; const float* alphap[2];
    __half* Hhi[2]; __half* Hlo[2];
};

// small: fts[m*1024 + fcol + n] (hi/lo), A hi+lo, B = W hi, K=512, ldb=512
__global__ void __launch_bounds__(256, 1)
gemm_small(SmallArgs ar, int K, long ldb)
{
    extern __shared__ __align__(1024) char smem[];
    const uint32_t sbase = smem_u32(smem);
    const int z = blockIdx.z;
    const __half* __restrict__ Ahi = ar.Ahi[z];
    const __half* __restrict__ Alo = ar.Alo[z];
    const __half* __restrict__ Bhi = ar.Bhi[z];
    __half* __restrict__ Fhi = ar.Fhi[z];
    __half* __restrict__ Flo = ar.Flo[z];
    const long lda = ar.lda[z], aofs = ar.aofs[z], fcol = ar.fcol[z];

    const int tid  = threadIdx.x;
    const int lane = tid & 31;
    const int wid  = tid >> 5;
    const int wm   = wid & 1;
    const int wn   = wid >> 1;
    const long arow = (long)blockIdx.y * 128;
    const long bn0  = (long)blockIdx.x * 128;
    const int  nk   = K >> 6;

    auto load_stage = [&](int st, int kc){
        uint32_t base = sbase + st * STG_BYTES;
        const long ka = aofs + (long)kc * 64;
        const long kb = (long)kc * 64;
        #pragma unroll
        for (int s = 0; s < 4; ++s){
            int idx = tid + 256 * s;
            int r = idx >> 3, u = idx & 7;
            uint32_t sw = (uint32_t)(r * 128 + ((u ^ (r & 7)) << 4));
            cp16(base + sw,         Ahi + (arow + r) * lda + ka + u * 8);
            cp16(base + 16384 + sw, Alo + (arow + r) * lda + ka + u * 8);
        }
        #pragma unroll
        for (int s = 0; s < 4; ++s){
            int idx = tid + 256 * s;
            int r = idx >> 4, u = idx & 15;
            uint32_t sw = (uint32_t)(r * 256 + ((u ^ (r & 7)) << 4));
            cp16(base + 32768 + sw, Bhi + (kb + r) * ldb + bn0 + u * 8);
        }
        cp_commit();
    };

    float acc[4][4][4];
    #pragma unroll
    for (int i = 0; i < 4; ++i)
        #pragma unroll
        for (int j = 0; j < 4; ++j)
            #pragma unroll
            for (int q = 0; q < 4; ++q) acc[i][j][q] = 0.f;

    load_stage(0, 0);
    load_stage(1, 1);

    const int l16 = lane & 15, l2 = lane >> 4;
    const int bkr  = lane & 15;
    const int bnu0 = (wn * 32) >> 3;

    for (int kt = 0; kt < nk; ++kt){
        cp_wait1();
        __syncthreads();
        if (kt + 2 < nk) load_stage((kt + 2) % 3, kt + 2);
        else cp_commit();

        const uint32_t sb = sbase + (kt % 3) * STG_BYTES;
        #pragma unroll
        for (int ks = 0; ks < 4; ++ks){
            uint32_t aH[4][4], aL[4][4], bH[4][2];
            #pragma unroll
            for (int mt = 0; mt < 4; ++mt){
                int mr = wm * 64 + mt * 16 + l16;
                uint32_t ad = sb + mr * 128 + (((ks * 2 + l2) ^ (mr & 7)) << 4);
                ldsm_x4(aH[mt][0], aH[mt][1], aH[mt][2], aH[mt][3], ad);
                ldsm_x4(aL[mt][0], aL[mt][1], aL[mt][2], aL[mt][3], ad + 16384);
            }
            #pragma unroll
            for (int p = 0; p < 2; ++p){
                int kr = ks * 16 + bkr;
                int nu = bnu0 + p * 2 + l2;
                uint32_t ad = sb + 32768 + kr * 256 + ((nu ^ (kr & 7)) << 4);
                ldsm_x4_t(bH[2*p][0], bH[2*p][1], bH[2*p+1][0], bH[2*p+1][1], ad);
            }
            #pragma unroll
            for (int mt = 0; mt < 4; ++mt)
                #pragma unroll
                for (int nt = 0; nt < 4; ++nt){
                    mma16816(acc[mt][nt], aH[mt], bH[nt][0], bH[nt][1]);
                    mma16816(acc[mt][nt], aL[mt], bH[nt][0], bH[nt][1]);
                }
        }
    }

    const int g  = lane >> 2;
    const int cp = (lane & 3) * 2;
    #pragma unroll
    for (int mt = 0; mt < 4; ++mt){
        #pragma unroll
        for (int nt = 0; nt < 4; ++nt){
            long n = fcol + bn0 + wn * 32 + nt * 8 + cp;
            #pragma unroll
            for (int h = 0; h < 2; ++h){
                long m = arow + wm * 64 + mt * 16 + g + h * 8;
                float v0 = acc[mt][nt][2*h + 0];
                float v1 = acc[mt][nt][2*h + 1];
                __half h0 = __float2half_rn(v0);
                __half h1 = __float2half_rn(v1);
                __half q0 = __float2half_rn(v0 - __half2float(h0));
                __half q1 = __float2half_rn(v1 - __half2float(h1));
                *(__half2*)&Fhi[m * 1024 + n] = __halves2half2(h0, h1);
                *(__half2*)&Flo[m * 1024 + n] = __halves2half2(q0, q1);
            }
        }
    }
}

// big: prelu(A@B + bias) -> fp32 C0/C1 (split at n=512), optional h1 hi/lo.
// A = adj/diff hi only, B = fts hi+lo. K=8192, lda=8192, ldb=1024.
__global__ void __launch_bounds__(256, 1)
gemm_big(BigArgs ar, int K)
{
    extern __shared__ __align__(1024) char smem[];
    const uint32_t sbase = smem_u32(smem);
    const int z = blockIdx.z;
    const __half* __restrict__ Ahi = ar.Ahi[z];
    const __half* __restrict__ Bhi = ar.Bhi[z];
    const __half* __restrict__ Blo = ar.Blo[z];
    float* __restrict__ C0 = ar.C0[z];
    float* __restrict__ C1 = ar.C1[z];
    const float* __restrict__ bias = ar.bias[z];
    const float* __restrict__ alphap = ar.alphap[z];
    __half* __restrict__ Hhi = ar.Hhi[z];
    __half* __restrict__ Hlo = ar.Hlo[z];
    const long lda = 8192, ldb = 1024;

    const int tid  = threadIdx.x;
    const int lane = tid & 31;
    const int wid  = tid >> 5;
    const int wm   = wid & 1;
    const int wn   = wid >> 1;
    const long arow = (long)blockIdx.y * 128;
    const long bn0  = (long)blockIdx.x * 128;
    const int  nk   = K >> 6;

    auto load_stage = [&](int st, int kc){
        uint32_t base = sbase + st * STG_BYTES;
        const long ka = (long)kc * 64;
        const long kb = (long)kc * 64;
        #pragma unroll
        for (int s = 0; s < 4; ++s){
            int idx = tid + 256 * s;
            int r = idx >> 3, u = idx & 7;
            uint32_t sw = (uint32_t)(r * 128 + ((u ^ (r & 7)) << 4));
            cp16(base + sw, Ahi + (arow + r) * lda + ka + u * 8);
        }
        #pragma unroll
        for (int s = 0; s < 4; ++s){
            int idx = tid + 256 * s;
            int r = idx >> 4, u = idx & 15;
            uint32_t sw = (uint32_t)(r * 256 + ((u ^ (r & 7)) << 4));
            cp16(base + 16384 + sw, Bhi + (kb + r) * ldb + bn0 + u * 8);
            cp16(base + 32768 + sw, Blo + (kb + r) * ldb + bn0 + u * 8);
        }
        cp_commit();
    };

    float acc[4][4][4];
    #pragma unroll
    for (int i = 0; i < 4; ++i)
        #pragma unroll
        for (int j = 0; j < 4; ++j)
            #pragma unroll
            for (int q = 0; q < 4; ++q) acc[i][j][q] = 0.f;

    load_stage(0, 0);
    load_stage(1, 1);

    const int l16 = lane & 15, l2 = lane >> 4;
    const int bkr  = lane & 15;
    const int bnu0 = (wn * 32) >> 3;

    for (int kt = 0; kt < nk; ++kt){
        cp_wait1();
        __syncthreads();
        if (kt + 2 < nk) load_stage((kt + 2) % 3, kt + 2);
        else cp_commit();

        const uint32_t sb = sbase + (kt % 3) * STG_BYTES;
        #pragma unroll
        for (int ks = 0; ks < 4; ++ks){
            uint32_t aH[4][4], bH[4][2], bL[4][2];
            #pragma unroll
            for (int mt = 0; mt < 4; ++mt){
                int mr = wm * 64 + mt * 16 + l16;
                uint32_t ad = sb + mr * 128 + (((ks * 2 + l2) ^ (mr & 7)) << 4);
                ldsm_x4(aH[mt][0], aH[mt][1], aH[mt][2], aH[mt][3], ad);
            }
            #pragma unroll
            for (int p = 0; p < 2; ++p){
                int kr = ks * 16 + bkr;
                int nu = bnu0 + p * 2 + l2;
                uint32_t ad = sb + 16384 + kr * 256 + ((nu ^ (kr & 7)) << 4);
                ldsm_x4_t(bH[2*p][0], bH[2*p][1], bH[2*p+1][0], bH[2*p+1][1], ad);
                ldsm_x4_t(bL[2*p][0], bL[2*p][1], bL[2*p+1][0], bL[2*p+1][1], ad + 16384);
            }
            #pragma unroll
            for (int mt = 0; mt < 4; ++mt)
                #pragma unroll
                for (int nt = 0; nt < 4; ++nt){
                    mma16816(acc[mt][nt], aH[mt], bH[nt][0], bH[nt][1]);
                    mma16816(acc[mt][nt], aH[mt], bL[nt][0], bL[nt][1]);
                }
        }
    }

    const int g  = lane >> 2;
    const int cp = (lane & 3) * 2;
    const float al = *alphap;
    #pragma unroll
    for (int mt = 0; mt < 4; ++mt){
        #pragma unroll
        for (int nt = 0; nt < 4; ++nt){
            long n  = bn0 + wn * 32 + nt * 8 + cp;
            int  nc = (int)(n & 511);
            float b0 = bias[nc], b1 = bias[nc + 1];
            float* C = (n < 512) ? C0 : C1;
            #pragma unroll
            for (int h = 0; h < 2; ++h){
                long m = arow + wm * 64 + mt * 16 + g + h * 8;
                float v0 = acc[mt][nt][2*h + 0] + b0;
                float v1 = acc[mt][nt][2*h + 1] + b1;
                v0 = (v0 >= 0.f) ? v0 : al * v0;
                v1 = (v1 >= 0.f) ? v1 : al * v1;
                *(float2*)&C[m * 512 + nc] = make_float2(v0, v1);
                if (Hhi){
                    __half h0 = __float2half_rn(v0);
                    __half h1 = __float2half_rn(v1);
                    __half q0 = __float2half_rn(v0 - __half2float(h0));
                    __half q1 = __float2half_rn(v1 - __half2float(h1));
                    *(__half2*)&Hhi[m * 1024 + n] = __halves2half2(h0, h1);
                    *(__half2*)&Hlo[m * 1024 + n] = __halves2half2(q0, q1);
                }
            }
        }
    }
}

extern "C" void kernel_launch(void* const* d_in, const int* in_sizes, int n_in,
                              void* d_out, int out_size)
{
    const float* seq_pos = (const float*)d_in[0];
    const float* seq_neg = (const float*)d_in[1];
    const float* adj     = (const float*)d_in[2];
    const float* diff    = (const float*)d_in[3];
    const float* W1a = (const float*)d_in[4];
    const float* W1d = (const float*)d_in[5];
    const float* W2a = (const float*)d_in[6];
    const float* W2d = (const float*)d_in[7];
    const float* b1a = (const float*)d_in[8];
    const float* b1d = (const float*)d_in[9];
    const float* b2a = (const float*)d_in[10];
    const float* b2d = (const float*)d_in[11];
    const float* al1a = (const float*)d_in[12];
    const float* al1d = (const float*)d_in[13];
    const float* al2a = (const float*)d_in[14];
    const float* al2d = (const float*)d_in[15];

    float* out = (float*)d_out;
    const size_t CHN = (size_t)8192 * 512;

    __half *adjHi,*difHi,*spHi,*spLo,*snHi,*snLo,*wHi;
    __half *ftAHi,*ftALo,*ftDHi,*ftDLo,*hAHi,*hALo,*hDHi,*hDLo;
    cudaGetSymbolAddress((void**)&adjHi, g_adjHi);
    cudaGetSymbolAddress((void**)&difHi, g_difHi);
    cudaGetSymbolAddress((void**)&spHi,  g_spHi);
    cudaGetSymbolAddress((void**)&spLo,  g_spLo);
    cudaGetSymbolAddress((void**)&snHi,  g_snHi);
    cudaGetSymbolAddress((void**)&snLo,  g_snLo);
    cudaGetSymbolAddress((void**)&wHi,   g_wHi);
    cudaGetSymbolAddress((void**)&ftAHi, g_ftAHi);
    cudaGetSymbolAddress((void**)&ftALo, g_ftALo);
    cudaGetSymbolAddress((void**)&ftDHi, g_ftDHi);
    cudaGetSymbolAddress((void**)&ftDLo, g_ftDLo);
    cudaGetSymbolAddress((void**)&hAHi,  g_hAHi);
    cudaGetSymbolAddress((void**)&hALo,  g_hALo);
    cudaGetSymbolAddress((void**)&hDHi,  g_hDHi);
    cudaGetSymbolAddress((void**)&hDLo,  g_hDLo);

    cudaFuncSetAttribute(gemm_small, cudaFuncAttributeMaxDynamicSharedMemorySize, SMEM_DYN);
    cudaFuncSetAttribute(gemm_big,   cudaFuncAttributeMaxDynamicSharedMemorySize, SMEM_DYN);

    // one fused conversion launch
    {
        size_t total_vec4 = (2*NEL_ADJ + 2*NEL_SEQ + 4*NEL_W) / 4;
        int blocks = (int)((total_vec4 + 255) / 256);
        fused_split<<<blocks, 256>>>(adj, diff, seq_pos, seq_neg, W1a, W1d, W2a, W2d,
                                     adjHi, difHi, spHi, spLo, snHi, snLo, wHi);
    }

    dim3 blk(256);
    dim3 gS(4, 64, 4);   // 4 small gemms batched
    dim3 gB(8, 64, 2);   // 2 big gemms batched

    // layer 1 small: fts = seq @ W1 (pos cols 0-511, neg 512-1023)
    {
        SmallArgs a;
        a.Ahi[0]=spHi; a.Alo[0]=spLo; a.Ahi[1]=snHi; a.Alo[1]=snLo;
        a.Ahi[2]=spHi; a.Alo[2]=spLo; a.Ahi[3]=snHi; a.Alo[3]=snLo;
        for (int i=0;i<4;++i){ a.lda[i]=512; a.aofs[i]=0; }
        a.Bhi[0]=wHi+0*NEL_W; a.Bhi[1]=wHi+0*NEL_W;
        a.Bhi[2]=wHi+1*NEL_W; a.Bhi[3]=wHi+1*NEL_W;
        a.Fhi[0]=ftAHi; a.Flo[0]=ftALo; a.Fhi[1]=ftAHi; a.Flo[1]=ftALo;
        a.Fhi[2]=ftDHi; a.Flo[2]=ftDLo; a.Fhi[3]=ftDHi; a.Flo[3]=ftDLo;
        a.fcol[0]=0; a.fcol[1]=512; a.fcol[2]=0; a.fcol[3]=512;
        gemm_small<<<gS, blk, SMEM_DYN>>>(a, 512, 512);
    }

    // layer 1 big: h1 = prelu(A @ fts + b), also emit h1 fp16 hi/lo
    {
        BigArgs a;
        a.Ahi[0]=adjHi; a.Ahi[1]=difHi;
        a.Bhi[0]=ftAHi; a.Blo[0]=ftALo; a.Bhi[1]=ftDHi; a.Blo[1]=ftDLo;
        a.C0[0]=out+0*CHN; a.C1[0]=out+4*CHN;
        a.C0[1]=out+1*CHN; a.C1[1]=out+5*CHN;
        a.bias[0]=b1a; a.alphap[0]=al1a; a.bias[1]=b1d; a.alphap[1]=al1d;
        a.Hhi[0]=hAHi; a.Hlo[0]=hALo; a.Hhi[1]=hDHi; a.Hlo[1]=hDLo;
        gemm_big<<<gB, blk, SMEM_DYN>>>(a, 8192);
    }

    // layer 2 small: fts2 = h1 @ W2
    {
        SmallArgs a;
        a.Ahi[0]=hAHi; a.Alo[0]=hALo; a.Ahi[1]=hAHi; a.Alo[1]=hALo;
        a.Ahi[2]=hDHi; a.Alo[2]=hDLo; a.Ahi[3]=hDHi; a.Alo[3]=hDLo;
        for (int i=0;i<4;++i) a.lda[i]=1024;
        a.aofs[0]=0; a.aofs[1]=512; a.aofs[2]=0; a.aofs[3]=512;
        a.Bhi[0]=wHi+2*NEL_W; a.Bhi[1]=wHi+2*NEL_W;
        a.Bhi[2]=wHi+3*NEL_W; a.Bhi[3]=wHi+3*NEL_W;
        a.Fhi[0]=ftAHi; a.Flo[0]=ftALo; a.Fhi[1]=ftAHi; a.Flo[1]=ftALo;
        a.Fhi[2]=ftDHi; a.Flo[2]=ftDLo; a.Fhi[3]=ftDHi; a.Flo[3]=ftDLo;
        a.fcol[0]=0; a.fcol[1]=512; a.fcol[2]=0; a.fcol[3]=512;
        gemm_small<<<gS, blk, SMEM_DYN>>>(a, 512, 512);
    }

    // layer 2 big
    {
        BigArgs a;
        a.Ahi[0]=adjHi; a.Ahi[1]=difHi;
        a.Bhi[0]=ftAHi; a.Blo[0]=ftALo; a.Bhi[1]=ftDHi; a.Blo[1]=ftDLo;
        a.C0[0]=out+2*CHN; a.C1[0]=out+6*CHN;
        a.C0[1]=out+3*CHN; a.C1[1]=out+7*CHN;
        a.bias[0]=b2a; a.alphap[0]=al2a; a.bias[1]=b2d; a.alphap[1]=al2d;
        a.Hhi[0]=nullptr; a.Hlo[0]=nullptr; a.Hhi[1]=nullptr; a.Hlo[1]=nullptr;
        gemm_big<<<gB, blk, SMEM_DYN>>>(a, 8192);
    }
}

// round 12
// speedup vs baseline: 5.7887x; 1.0046x over previous
#include <cuda_runtime.h>
#include <cuda_fp16.h>
#include <stdint.h>

// Model_63256278335531: 2-layer dual-GCN via fp16x2 mma.sync (HMMA) GEMMs.
// Big GEMM:   D = Ah*Bh + Ah*Bl   (A = adj/diff hi-only, B = fts hi+lo)
// Small GEMM: D = Ah*Bh + Al*Bh   (A = seq/h1 hi+lo,     B = W hi-only)
// fp32 register accumulate. R11: register double-buffered fragments +
// dependent-MMA separation in the inner loop.

#define NEL_ADJ (8192ull*8192ull)
#define NEL_SEQ (8192ull*512ull)
#define NEL_W   (512ull*512ull)
#define NEL_FTS (8192ull*1024ull)

__device__ __align__(16) __half g_adjHi[NEL_ADJ];
__device__ __align__(16) __half g_difHi[NEL_ADJ];
__device__ __align__(16) __half g_spHi[NEL_SEQ], g_spLo[NEL_SEQ];
__device__ __align__(16) __half g_snHi[NEL_SEQ], g_snLo[NEL_SEQ];
__device__ __align__(16) __half g_wHi[4][NEL_W];
// fts as B of big GEMM: [K=8192][N=1024] (pos cols 0-511, neg 512-1023)
__device__ __align__(16) __half g_ftAHi[NEL_FTS], g_ftALo[NEL_FTS];
__device__ __align__(16) __half g_ftDHi[NEL_FTS], g_ftDLo[NEL_FTS];
// h1 packed [M=8192][1024]: A of layer-2 small GEMM
__device__ __align__(16) __half g_hAHi[NEL_FTS], g_hALo[NEL_FTS];
__device__ __align__(16) __half g_hDHi[NEL_FTS], g_hDLo[NEL_FTS];

__device__ __forceinline__ uint32_t smem_u32(const void* p){
    uint32_t a;
    asm("{ .reg .u64 t; cvta.to.shared.u64 t, %1; cvt.u32.u64 %0, t; }"
        : "=r"(a) : "l"(p));
    return a;
}
__device__ __forceinline__ void cp16(uint32_t dst, const void* src){
    asm volatile("{ .reg .u64 g; cvta.to.global.u64 g, %1;"
                 " cp.async.cg.shared.global [%0], [g], 16; }"
                 :: "r"(dst), "l"(src) : "memory");
}
__device__ __forceinline__ void cp_commit(){
    asm volatile("cp.async.commit_group;" ::: "memory");
}
__device__ __forceinline__ void cp_wait1(){
    asm volatile("cp.async.wait_group 1;" ::: "memory");
}
__device__ __forceinline__ void ldsm_x4(uint32_t& r0, uint32_t& r1,
                                        uint32_t& r2, uint32_t& r3, uint32_t a){
    asm volatile("ldmatrix.sync.aligned.m8n8.x4.shared.b16 {%0,%1,%2,%3}, [%4];"
                 : "=r"(r0), "=r"(r1), "=r"(r2), "=r"(r3) : "r"(a));
}
__device__ __forceinline__ void ldsm_x4_t(uint32_t& r0, uint32_t& r1,
                                          uint32_t& r2, uint32_t& r3, uint32_t a){
    asm volatile("ldmatrix.sync.aligned.m8n8.x4.trans.shared.b16 {%0,%1,%2,%3}, [%4];"
                 : "=r"(r0), "=r"(r1), "=r"(r2), "=r"(r3) : "r"(a));
}
__device__ __forceinline__ void mma16816(float* c, const uint32_t* a,
                                         uint32_t b0, uint32_t b1){
    asm volatile("mma.sync.aligned.m16n8k16.row.col.f32.f16.f16.f32 "
                 "{%0,%1,%2,%3}, {%4,%5,%6,%7}, {%8,%9}, {%0,%1,%2,%3};"
                 : "+f"(c[0]), "+f"(c[1]), "+f"(c[2]), "+f"(c[3])
                 : "r"(a[0]), "r"(a[1]), "r"(a[2]), "r"(a[3]), "r"(b0), "r"(b1));
}

// ---- fused conversion: adj/dif/W -> fp16 hi; seq -> fp16 hi+lo --------------
__device__ __forceinline__ void cv_hi(const float* __restrict__ x,
                                      __half* __restrict__ hi, size_t i)
{
    float4 v = *(const float4*)(x + i);
    __half2* H = (__half2*)(hi + i);
    H[0] = __halves2half2(__float2half_rn(v.x), __float2half_rn(v.y));
    H[1] = __halves2half2(__float2half_rn(v.z), __float2half_rn(v.w));
}
__device__ __forceinline__ void cv_hl(const float* __restrict__ x,
                                      __half* __restrict__ hi,
                                      __half* __restrict__ lo, size_t i)
{
    float4 v = *(const float4*)(x + i);
    __half h0 = __float2half_rn(v.x), h1 = __float2half_rn(v.y);
    __half h2 = __float2half_rn(v.z), h3 = __float2half_rn(v.w);
    __half l0 = __float2half_rn(v.x - __half2float(h0));
    __half l1 = __float2half_rn(v.y - __half2float(h1));
    __half l2 = __float2half_rn(v.z - __half2float(h2));
    __half l3 = __float2half_rn(v.w - __half2float(h3));
    __half2* H = (__half2*)(hi + i);
    H[0] = __halves2half2(h0, h1); H[1] = __halves2half2(h2, h3);
    __half2* L = (__half2*)(lo + i);
    L[0] = __halves2half2(l0, l1); L[1] = __halves2half2(l2, l3);
}

__global__ void fused_split(const float* __restrict__ adj, const float* __restrict__ dif,
                            const float* __restrict__ sp,  const float* __restrict__ sn,
                            const float* __restrict__ w0,  const float* __restrict__ w1,
                            const float* __restrict__ w2,  const float* __restrict__ w3,
                            __half* adjHi, __half* difHi,
                            __half* spHi, __half* spLo,
                            __half* snHi, __half* snLo, __half* wHi)
{
    size_t o = ((size_t)blockIdx.x * blockDim.x + threadIdx.x) * 4;
    if (o < NEL_ADJ) { cv_hi(adj, adjHi, o); return; } o -= NEL_ADJ;
    if (o < NEL_ADJ) { cv_hi(dif, difHi, o); return; } o -= NEL_ADJ;
    if (o < NEL_SEQ) { cv_hl(sp, spHi, spLo, o); return; } o -= NEL_SEQ;
    if (o < NEL_SEQ) { cv_hl(sn, snHi, snLo, o); return; } o -= NEL_SEQ;
    if (o < NEL_W) { cv_hi(w0, wHi + 0*NEL_W, o); return; } o -= NEL_W;
    if (o < NEL_W) { cv_hi(w1, wHi + 1*NEL_W, o); return; } o -= NEL_W;
    if (o < NEL_W) { cv_hi(w2, wHi + 2*NEL_W, o); return; } o -= NEL_W;
    if (o < NEL_W) { cv_hi(w3, wHi + 3*NEL_W, o); }
}

// ---- GEMM core --------------------------------------------------------------
// CTA 128(M) x 128(N), K-stage 64, 3-stage cp.async pipeline, 1 sync/iter.
// 8 warps: wm = wid&1 (M-halves of 64), wn = wid>>1 (N-quarters of 32).
// Stage 48KB. big: AH@0 BH@16K BL@32K.  small: AH@0 AL@16K BH@32K.
// A rows 128B (8x16B units), swizzle unit u -> u ^ (row&7).
// B rows 256B (16x16B units), same low-3-bit XOR swizzle.
// Inner loop: fragments double-buffered in registers; LDSM for slice ks+1
// issued before MMAs of slice ks; bH/bL MMAs to the same acc separated.
#define STG_BYTES 49152
#define SMEM_DYN  (3*STG_BYTES)

struct SmallArgs {
    const __half* Ahi[4]; const __half* Alo[4];
    long lda[4]; long aofs[4];
    const __half* Bhi[4];
    __half* Fhi[4]; __half* Flo[4];
    long fcol[4];
};
struct BigArgs {
    const __half* Ahi[2];
    const __half* Bhi[2]; const __half* Blo[2];
    float* C0[2]; float* C1[2];
    const float* bias[2]; const float* alphap[2];
    __half* Hhi[2]; __half* Hlo[2];
};

// small: fts[m*1024 + fcol + n] (hi/lo), A hi+lo, B = W hi, K=512, ldb=512
__global__ void __launch_bounds__(256, 1)
gemm_small(SmallArgs ar, int K, long ldb)
{
    extern __shared__ __align__(1024) char smem[];
    const uint32_t sbase = smem_u32(smem);
    const int z = blockIdx.z;
    const __half* __restrict__ Ahi = ar.Ahi[z];
    const __half* __restrict__ Alo = ar.Alo[z];
    const __half* __restrict__ Bhi = ar.Bhi[z];
    __half* __restrict__ Fhi = ar.Fhi[z];
    __half* __restrict__ Flo = ar.Flo[z];
    const long lda = ar.lda[z], aofs = ar.aofs[z], fcol = ar.fcol[z];

    const int tid  = threadIdx.x;
    const int lane = tid & 31;
    const int wid  = tid >> 5;
    const int wm   = wid & 1;
    const int wn   = wid >> 1;
    const long arow = (long)blockIdx.y * 128;
    const long bn0  = (long)blockIdx.x * 128;
    const int  nk   = K >> 6;

    auto load_stage = [&](int st, int kc){
        uint32_t base = sbase + st * STG_BYTES;
        const long ka = aofs + (long)kc * 64;
        const long kb = (long)kc * 64;
        #pragma unroll
        for (int s = 0; s < 4; ++s){
            int idx = tid + 256 * s;
            int r = idx >> 3, u = idx & 7;
            uint32_t sw = (uint32_t)(r * 128 + ((u ^ (r & 7)) << 4));
            cp16(base + sw,         Ahi + (arow + r) * lda + ka + u * 8);
            cp16(base + 16384 + sw, Alo + (arow + r) * lda + ka + u * 8);
        }
        #pragma unroll
        for (int s = 0; s < 4; ++s){
            int idx = tid + 256 * s;
            int r = idx >> 4, u = idx & 15;
            uint32_t sw = (uint32_t)(r * 256 + ((u ^ (r & 7)) << 4));
            cp16(base + 32768 + sw, Bhi + (kb + r) * ldb + bn0 + u * 8);
        }
        cp_commit();
    };

    float acc[4][4][4];
    #pragma unroll
    for (int i = 0; i < 4; ++i)
        #pragma unroll
        for (int j = 0; j < 4; ++j)
            #pragma unroll
            for (int q = 0; q < 4; ++q) acc[i][j][q] = 0.f;

    load_stage(0, 0);
    load_stage(1, 1);

    const int l16 = lane & 15, l2 = lane >> 4;
    const int bkr  = lane & 15;
    const int bnu0 = (wn * 32) >> 3;

    uint32_t aH[2][4][4], aL[2][4][4], bH[2][4][2];

    auto load_frags = [&](int buf, uint32_t sb, int ks){
        #pragma unroll
        for (int mt = 0; mt < 4; ++mt){
            int mr = wm * 64 + mt * 16 + l16;
            uint32_t ad = sb + mr * 128 + (((ks * 2 + l2) ^ (mr & 7)) << 4);
            ldsm_x4(aH[buf][mt][0], aH[buf][mt][1], aH[buf][mt][2], aH[buf][mt][3], ad);
            ldsm_x4(aL[buf][mt][0], aL[buf][mt][1], aL[buf][mt][2], aL[buf][mt][3], ad + 16384);
        }
        #pragma unroll
        for (int p = 0; p < 2; ++p){
            int kr = ks * 16 + bkr;
            int nu = bnu0 + p * 2 + l2;
            uint32_t ad = sb + 32768 + kr * 256 + ((nu ^ (kr & 7)) << 4);
            ldsm_x4_t(bH[buf][2*p][0], bH[buf][2*p][1], bH[buf][2*p+1][0], bH[buf][2*p+1][1], ad);
        }
    };

    for (int kt = 0; kt < nk; ++kt){
        cp_wait1();
        __syncthreads();
        if (kt + 2 < nk) load_stage((kt + 2) % 3, kt + 2);
        else cp_commit();

        const uint32_t sb = sbase + (kt % 3) * STG_BYTES;
        load_frags(0, sb, 0);
        #pragma unroll
        for (int ks = 0; ks < 4; ++ks){
            const int cur = ks & 1;
            if (ks < 3) load_frags(cur ^ 1, sb, ks + 1);
            #pragma unroll
            for (int mt = 0; mt < 4; ++mt){
                #pragma unroll
                for (int nt = 0; nt < 4; ++nt)
                    mma16816(acc[mt][nt], aH[cur][mt], bH[cur][nt][0], bH[cur][nt][1]);
                #pragma unroll
                for (int nt = 0; nt < 4; ++nt)
                    mma16816(acc[mt][nt], aL[cur][mt], bH[cur][nt][0], bH[cur][nt][1]);
            }
        }
    }

    const int g  = lane >> 2;
    const int cp = (lane & 3) * 2;
    #pragma unroll
    for (int mt = 0; mt < 4; ++mt){
        #pragma unroll
        for (int nt = 0; nt < 4; ++nt){
            long n = fcol + bn0 + wn * 32 + nt * 8 + cp;
            #pragma unroll
            for (int h = 0; h < 2; ++h){
                long m = arow + wm * 64 + mt * 16 + g + h * 8;
                float v0 = acc[mt][nt][2*h + 0];
                float v1 = acc[mt][nt][2*h + 1];
                __half h0 = __float2half_rn(v0);
                __half h1 = __float2half_rn(v1);
                __half q0 = __float2half_rn(v0 - __half2float(h0));
                __half q1 = __float2half_rn(v1 - __half2float(h1));
                *(__half2*)&Fhi[m * 1024 + n] = __halves2half2(h0, h1);
                *(__half2*)&Flo[m * 1024 + n] = __halves2half2(q0, q1);
            }
        }
    }
}

// big: prelu(A@B + bias) -> fp32 C0/C1 (split at n=512), optional h1 hi/lo.
// A = adj/diff hi only, B = fts hi+lo. K=8192, lda=8192, ldb=1024.
__global__ void __launch_bounds__(256, 1)
gemm_big(BigArgs ar, int K)
{
    extern __shared__ __align__(1024) char smem[];
    const uint32_t sbase = smem_u32(smem);
    const int z = blockIdx.z;
    const __half* __restrict__ Ahi = ar.Ahi[z];
    const __half* __restrict__ Bhi = ar.Bhi[z];
    const __half* __restrict__ Blo = ar.Blo[z];
    float* __restrict__ C0 = ar.C0[z];
    float* __restrict__ C1 = ar.C1[z];
    const float* __restrict__ bias = ar.bias[z];
    const float* __restrict__ alphap = ar.alphap[z];
    __half* __restrict__ Hhi = ar.Hhi[z];
    __half* __restrict__ Hlo = ar.Hlo[z];
    const long lda = 8192, ldb = 1024;

    const int tid  = threadIdx.x;
    const int lane = tid & 31;
    const int wid  = tid >> 5;
    const int wm   = wid & 1;
    const int wn   = wid >> 1;
    const long arow = (long)blockIdx.y * 128;
    const long bn0  = (long)blockIdx.x * 128;
    const int  nk   = K >> 6;

    auto load_stage = [&](int st, int kc){
        uint32_t base = sbase + st * STG_BYTES;
        const long ka = (long)kc * 64;
        const long kb = (long)kc * 64;
        #pragma unroll
        for (int s = 0; s < 4; ++s){
            int idx = tid + 256 * s;
            int r = idx >> 3, u = idx & 7;
            uint32_t sw = (uint32_t)(r * 128 + ((u ^ (r & 7)) << 4));
            cp16(base + sw, Ahi + (arow + r) * lda + ka + u * 8);
        }
        #pragma unroll
        for (int s = 0; s < 4; ++s){
            int idx = tid + 256 * s;
            int r = idx >> 4, u = idx & 15;
            uint32_t sw = (uint32_t)(r * 256 + ((u ^ (r & 7)) << 4));
            cp16(base + 16384 + sw, Bhi + (kb + r) * ldb + bn0 + u * 8);
            cp16(base + 32768 + sw, Blo + (kb + r) * ldb + bn0 + u * 8);
        }
        cp_commit();
    };

    float acc[4][4][4];
    #pragma unroll
    for (int i = 0; i < 4; ++i)
        #pragma unroll
        for (int j = 0; j < 4; ++j)
            #pragma unroll
            for (int q = 0; q < 4; ++q) acc[i][j][q] = 0.f;

    load_stage(0, 0);
    load_stage(1, 1);

    const int l16 = lane & 15, l2 = lane >> 4;
    const int bkr  = lane & 15;
    const int bnu0 = (wn * 32) >> 3;

    uint32_t aH[2][4][4], bH[2][4][2], bL[2][4][2];

    auto load_frags = [&](int buf, uint32_t sb, int ks){
        #pragma unroll
        for (int mt = 0; mt < 4; ++mt){
            int mr = wm * 64 + mt * 16 + l16;
            uint32_t ad = sb + mr * 128 + (((ks * 2 + l2) ^ (mr & 7)) << 4);
            ldsm_x4(aH[buf][mt][0], aH[buf][mt][1], aH[buf][mt][2], aH[buf][mt][3], ad);
        }
        #pragma unroll
        for (int p = 0; p < 2; ++p){
            int kr = ks * 16 + bkr;
            int nu = bnu0 + p * 2 + l2;
            uint32_t ad = sb + 16384 + kr * 256 + ((nu ^ (kr & 7)) << 4);
            ldsm_x4_t(bH[buf][2*p][0], bH[buf][2*p][1], bH[buf][2*p+1][0], bH[buf][2*p+1][1], ad);
            ldsm_x4_t(bL[buf][2*p][0], bL[buf][2*p][1], bL[buf][2*p+1][0], bL[buf][2*p+1][1], ad + 16384);
        }
    };

    for (int kt = 0; kt < nk; ++kt){
        cp_wait1();
        __syncthreads();
        if (kt + 2 < nk) load_stage((kt + 2) % 3, kt + 2);
        else cp_commit();

        const uint32_t sb = sbase + (kt % 3) * STG_BYTES;
        load_frags(0, sb, 0);
        #pragma unroll
        for (int ks = 0; ks < 4; ++ks){
            const int cur = ks & 1;
            if (ks < 3) load_frags(cur ^ 1, sb, ks + 1);
            #pragma unroll
            for (int mt = 0; mt < 4; ++mt){
                #pragma unroll
                for (int nt = 0; nt < 4; ++nt)
                    mma16816(acc[mt][nt], aH[cur][mt], bH[cur][nt][0], bH[cur][nt][1]);
                #pragma unroll
                for (int nt = 0; nt < 4; ++nt)
                    mma16816(acc[mt][nt], aH[cur][mt], bL[cur][nt][0], bL[cur][nt][1]);
            }
        }
    }

    const int g  = lane >> 2;
    const int cp = (lane & 3) * 2;
    const float al = *alphap;
    #pragma unroll
    for (int mt = 0; mt < 4; ++mt){
        #pragma unroll
        for (int nt = 0; nt < 4; ++nt){
            long n  = bn0 + wn * 32 + nt * 8 + cp;
            int  nc = (int)(n & 511);
            float b0 = bias[nc], b1 = bias[nc + 1];
            float* C = (n < 512) ? C0 : C1;
            #pragma unroll
            for (int h = 0; h < 2; ++h){
                long m = arow + wm * 64 + mt * 16 + g + h * 8;
                float v0 = acc[mt][nt][2*h + 0] + b0;
                float v1 = acc[mt][nt][2*h + 1] + b1;
                v0 = (v0 >= 0.f) ? v0 : al * v0;
                v1 = (v1 >= 0.f) ? v1 : al * v1;
                *(float2*)&C[m * 512 + nc] = make_float2(v0, v1);
                if (Hhi){
                    __half h0 = __float2half_rn(v0);
                    __half h1 = __float2half_rn(v1);
                    __half q0 = __float2half_rn(v0 - __half2float(h0));
                    __half q1 = __float2half_rn(v1 - __half2float(h1));
                    *(__half2*)&Hhi[m * 1024 + n] = __halves2half2(h0, h1);
                    *(__half2*)&Hlo[m * 1024 + n] = __halves2half2(q0, q1);
                }
            }
        }
    }
}

extern "C" void kernel_launch(void* const* d_in, const int* in_sizes, int n_in,
                              void* d_out, int out_size)
{
    const float* seq_pos = (const float*)d_in[0];
    const float* seq_neg = (const float*)d_in[1];
    const float* adj     = (const float*)d_in[2];
    const float* diff    = (const float*)d_in[3];
    const float* W1a = (const float*)d_in[4];
    const float* W1d = (const float*)d_in[5];
    const float* W2a = (const float*)d_in[6];
    const float* W2d = (const float*)d_in[7];
    const float* b1a = (const float*)d_in[8];
    const float* b1d = (const float*)d_in[9];
    const float* b2a = (const float*)d_in[10];
    const float* b2d = (const float*)d_in[11];
    const float* al1a = (const float*)d_in[12];
    const float* al1d = (const float*)d_in[13];
    const float* al2a = (const float*)d_in[14];
    const float* al2d = (const float*)d_in[15];

    float* out = (float*)d_out;
    const size_t CHN = (size_t)8192 * 512;

    __half *adjHi,*difHi,*spHi,*spLo,*snHi,*snLo,*wHi;
    __half *ftAHi,*ftALo,*ftDHi,*ftDLo,*hAHi,*hALo,*hDHi,*hDLo;
    cudaGetSymbolAddress((void**)&adjHi, g_adjHi);
    cudaGetSymbolAddress((void**)&difHi, g_difHi);
    cudaGetSymbolAddress((void**)&spHi,  g_spHi);
    cudaGetSymbolAddress((void**)&spLo,  g_spLo);
    cudaGetSymbolAddress((void**)&snHi,  g_snHi);
    cudaGetSymbolAddress((void**)&snLo,  g_snLo);
    cudaGetSymbolAddress((void**)&wHi,   g_wHi);
    cudaGetSymbolAddress((void**)&ftAHi, g_ftAHi);
    cudaGetSymbolAddress((void**)&ftALo, g_ftALo);
    cudaGetSymbolAddress((void**)&ftDHi, g_ftDHi);
    cudaGetSymbolAddress((void**)&ftDLo, g_ftDLo);
    cudaGetSymbolAddress((void**)&hAHi,  g_hAHi);
    cudaGetSymbolAddress((void**)&hALo,  g_hALo);
    cudaGetSymbolAddress((void**)&hDHi,  g_hDHi);
    cudaGetSymbolAddress((void**)&hDLo,  g_hDLo);

    cudaFuncSetAttribute(gemm_small, cudaFuncAttributeMaxDynamicSharedMemorySize, SMEM_DYN);
    cudaFuncSetAttribute(gemm_big,   cudaFuncAttributeMaxDynamicSharedMemorySize, SMEM_DYN);

    // one fused conversion launch
    {
        size_t total_vec4 = (2*NEL_ADJ + 2*NEL_SEQ + 4*NEL_W) / 4;
        int blocks = (int)((total_vec4 + 255) / 256);
        fused_split<<<blocks, 256>>>(adj, diff, seq_pos, seq_neg, W1a, W1d, W2a, W2d,
                                     adjHi, difHi, spHi, spLo, snHi, snLo, wHi);
    }

    dim3 blk(256);
    dim3 gS(4, 64, 4);   // 4 small gemms batched
    dim3 gB(8, 64, 2);   // 2 big gemms batched

    // layer 1 small: fts = seq @ W1 (pos cols 0-511, neg 512-1023)
    {
        SmallArgs a;
        a.Ahi[0]=spHi; a.Alo[0]=spLo; a.Ahi[1]=snHi; a.Alo[1]=snLo;
        a.Ahi[2]=spHi; a.Alo[2]=spLo; a.Ahi[3]=snHi; a.Alo[3]=snLo;
        for (int i=0;i<4;++i){ a.lda[i]=512; a.aofs[i]=0; }
        a.Bhi[0]=wHi+0*NEL_W; a.Bhi[1]=wHi+0*NEL_W;
        a.Bhi[2]=wHi+1*NEL_W; a.Bhi[3]=wHi+1*NEL_W;
        a.Fhi[0]=ftAHi; a.Flo[0]=ftALo; a.Fhi[1]=ftAHi; a.Flo[1]=ftALo;
        a.Fhi[2]=ftDHi; a.Flo[2]=ftDLo; a.Fhi[3]=ftDHi; a.Flo[3]=ftDLo;
        a.fcol[0]=0; a.fcol[1]=512; a.fcol[2]=0; a.fcol[3]=512;
        gemm_small<<<gS, blk, SMEM_DYN>>>(a, 512, 512);
    }

    // layer 1 big: h1 = prelu(A @ fts + b), also emit h1 fp16 hi/lo
    {
        BigArgs a;
        a.Ahi[0]=adjHi; a.Ahi[1]=difHi;
        a.Bhi[0]=ftAHi; a.Blo[0]=ftALo; a.Bhi[1]=ftDHi; a.Blo[1]=ftDLo;
        a.C0[0]=out+0*CHN; a.C1[0]=out+4*CHN;
        a.C0[1]=out+1*CHN; a.C1[1]=out+5*CHN;
        a.bias[0]=b1a; a.alphap[0]=al1a; a.bias[1]=b1d; a.alphap[1]=al1d;
        a.Hhi[0]=hAHi; a.Hlo[0]=hALo; a.Hhi[1]=hDHi; a.Hlo[1]=hDLo;
        gemm_big<<<gB, blk, SMEM_DYN>>>(a, 8192);
    }

    // layer 2 small: fts2 = h1 @ W2
    {
        SmallArgs a;
        a.Ahi[0]=hAHi; a.Alo[0]=hALo; a.Ahi[1]=hAHi; a.Alo[1]=hALo;
        a.Ahi[2]=hDHi; a.Alo[2]=hDLo; a.Ahi[3]=hDHi; a.Alo[3]=hDLo;
        for (int i=0;i<4;++i) a.lda[i]=1024;
        a.aofs[0]=0; a.aofs[1]=512; a.aofs[2]=0; a.aofs[3]=512;
        a.Bhi[0]=wHi+2*NEL_W; a.Bhi[1]=wHi+2*NEL_W;
        a.Bhi[2]=wHi+3*NEL_W; a.Bhi[3]=wHi+3*NEL_W;
        a.Fhi[0]=ftAHi; a.Flo[0]=ftALo; a.Fhi[1]=ftAHi; a.Flo[1]=ftALo;
        a.Fhi[2]=ftDHi; a.Flo[2]=ftDLo; a.Fhi[3]=ftDHi; a.Flo[3]=ftDLo;
        a.fcol[0]=0; a.fcol[1]=512; a.fcol[2]=0; a.fcol[3]=512;
        gemm_small<<<gS, blk, SMEM_DYN>>>(a, 512, 512);
    }

    // layer 2 big
    {
        BigArgs a;
        a.Ahi[0]=adjHi; a.Ahi[1]=difHi;
        a.Bhi[0]=ftAHi; a.Blo[0]=ftALo; a.Bhi[1]=ftDHi; a.Blo[1]=ftDLo;
        a.C0[0]=out+2*CHN; a.C1[0]=out+6*CHN;
        a.C0[1]=out+3*CHN; a.C1[1]=out+7*CHN;
        a.bias[0]=b2a; a.alphap[0]=al2a; a.bias[1]=b2d; a.alphap[1]=al2d;
        a.Hhi[0]=nullptr; a.Hlo[0]=nullptr; a.Hhi[1]=nullptr; a.Hlo[1]=nullptr;
        gemm_big<<<gB, blk, SMEM_DYN>>>(a, 8192);
    }
}